// round 11
// baseline (speedup 1.0000x reference)
#include <cuda_runtime.h>
#include <cuda_pipeline.h>
#include <cstdint>

#define B   32
#define HKV 8
#define G   4
#define HD  128
#define D   4096
#define NQ  4096
#define NKV 1024
#define NTOT 6144
#define L   2048
#define KSQ 16        // split-K for qkv gemm
#define KSW 32        // split-K for wo gemm
#define NSPLIT 4
#define SKEYS 8       // keys per attention stage
#define NSTAGE 4      // attention smem ring depth

__device__ float g_qkv_part[KSQ * B * NTOT];
__device__ float g_qkv[B * NTOT];
__device__ float g_att_part[B * HKV * NSPLIT * G * HD];
__device__ float g_att_s[B * HKV * NSPLIT * G];
__device__ float g_attn[B * NQ];
__device__ float g_out_part[KSW * B * D];

// -------------------- f32x2 packed helpers --------------------
__device__ __forceinline__ unsigned long long pack2(float lo, float hi) {
    unsigned long long r;
    asm("mov.b64 %0, {%1, %2};" : "=l"(r) : "f"(lo), "f"(hi));
    return r;
}
__device__ __forceinline__ unsigned long long mul2(unsigned long long a,
                                                   unsigned long long b) {
    unsigned long long r;
    asm("mul.rn.f32x2 %0, %1, %2;" : "=l"(r) : "l"(a), "l"(b));
    return r;
}
__device__ __forceinline__ void fma2(unsigned long long& acc, unsigned long long a,
                                     unsigned long long b) {
    asm("fma.rn.f32x2 %0, %1, %2, %0;" : "+l"(acc) : "l"(a), "l"(b));
}
__device__ __forceinline__ float2 unpack2(unsigned long long v) {
    float2 f;
    asm("mov.b64 {%0, %1}, %2;" : "=f"(f.x), "=f"(f.y) : "l"(v));
    return f;
}
__device__ __forceinline__ unsigned long long dup_lo(unsigned long long v) {
    float2 f = unpack2(v);
    return pack2(f.x, f.x);
}
__device__ __forceinline__ unsigned long long dup_hi(unsigned long long v) {
    float2 f = unpack2(v);
    return pack2(f.y, f.y);
}

// -------------------- GEMM core (R9 best config, unchanged) -----------------
__device__ __forceinline__ void gemm_core(
    const float* __restrict__ A,
    const float* __restrict__ W,
    int ldw, int wc0,
    float* __restrict__ C, int ldc,
    int k0, int nkt)
{
    __shared__ __align__(16) float Ws[2][16][260];
    __shared__ __align__(16) float As[2][16][36];

    const int tid = threadIdx.x;
    const int tx = tid & 31;
    const int ty = tid >> 5;

    const int wr = tid >> 3;
    const int wc = (tid & 7) * 4;
    const int am = tid >> 2;
    const int ak = (tid & 3) * 4;

    unsigned long long acc[4][8];
#pragma unroll
    for (int r = 0; r < 4; r++)
#pragma unroll
        for (int c = 0; c < 8; c++) acc[r][c] = 0ull;

    {
        const float* wsrc = W + (size_t)(k0 + wr) * ldw + wc0 + wc;
#pragma unroll
        for (int j = 0; j < 8; j++)
            __pipeline_memcpy_async(&Ws[0][wr][wc + j * 32], wsrc + j * 32, 16);
        __pipeline_commit();
        float4 av = *reinterpret_cast<const float4*>(A + am * 4096 + k0 + ak);
        As[0][ak + 0][am] = av.x;
        As[0][ak + 1][am] = av.y;
        As[0][ak + 2][am] = av.z;
        As[0][ak + 3][am] = av.w;
    }

    for (int kt = 0; kt < nkt; kt++) {
        const int cur = kt & 1;
        const int nb = cur ^ 1;
        float4 av2 = make_float4(0.f, 0.f, 0.f, 0.f);
        const bool more = (kt + 1 < nkt);
        if (more) {
            const int kg = k0 + (kt + 1) * 16;
            const float* wsrc = W + (size_t)(kg + wr) * ldw + wc0 + wc;
#pragma unroll
            for (int j = 0; j < 8; j++)
                __pipeline_memcpy_async(&Ws[nb][wr][wc + j * 32], wsrc + j * 32, 16);
            __pipeline_commit();
            av2 = *reinterpret_cast<const float4*>(A + am * 4096 + kg + ak);
            __pipeline_wait_prior(1);
        } else {
            __pipeline_wait_prior(0);
        }
        __syncthreads();

#pragma unroll
        for (int k = 0; k < 16; k++) {
            ulonglong2 b01 = *reinterpret_cast<const ulonglong2*>(&Ws[cur][k][tx * 4]);
            ulonglong2 b23 = *reinterpret_cast<const ulonglong2*>(&Ws[cur][k][128 + tx * 4]);
            ulonglong2 ap0 = *reinterpret_cast<const ulonglong2*>(&As[cur][k][ty * 8]);
            ulonglong2 ap1 = *reinterpret_cast<const ulonglong2*>(&As[cur][k][ty * 8 + 4]);
            unsigned long long d0 = dup_lo(b01.x), d1 = dup_hi(b01.x);
            unsigned long long d2 = dup_lo(b01.y), d3 = dup_hi(b01.y);
            unsigned long long d4 = dup_lo(b23.x), d5 = dup_hi(b23.x);
            unsigned long long d6 = dup_lo(b23.y), d7 = dup_hi(b23.y);
            fma2(acc[0][0], ap0.x, d0); fma2(acc[0][1], ap0.x, d1);
            fma2(acc[0][2], ap0.x, d2); fma2(acc[0][3], ap0.x, d3);
            fma2(acc[0][4], ap0.x, d4); fma2(acc[0][5], ap0.x, d5);
            fma2(acc[0][6], ap0.x, d6); fma2(acc[0][7], ap0.x, d7);
            fma2(acc[1][0], ap0.y, d0); fma2(acc[1][1], ap0.y, d1);
            fma2(acc[1][2], ap0.y, d2); fma2(acc[1][3], ap0.y, d3);
            fma2(acc[1][4], ap0.y, d4); fma2(acc[1][5], ap0.y, d5);
            fma2(acc[1][6], ap0.y, d6); fma2(acc[1][7], ap0.y, d7);
            fma2(acc[2][0], ap1.x, d0); fma2(acc[2][1], ap1.x, d1);
            fma2(acc[2][2], ap1.x, d2); fma2(acc[2][3], ap1.x, d3);
            fma2(acc[2][4], ap1.x, d4); fma2(acc[2][5], ap1.x, d5);
            fma2(acc[2][6], ap1.x, d6); fma2(acc[2][7], ap1.x, d7);
            fma2(acc[3][0], ap1.y, d0); fma2(acc[3][1], ap1.y, d1);
            fma2(acc[3][2], ap1.y, d2); fma2(acc[3][3], ap1.y, d3);
            fma2(acc[3][4], ap1.y, d4); fma2(acc[3][5], ap1.y, d5);
            fma2(acc[3][6], ap1.y, d6); fma2(acc[3][7], ap1.y, d7);
        }

        if (more) {
            As[nb][ak + 0][am] = av2.x;
            As[nb][ak + 1][am] = av2.y;
            As[nb][ak + 2][am] = av2.z;
            As[nb][ak + 3][am] = av2.w;
        }
        __syncthreads();
    }

#pragma unroll
    for (int rp = 0; rp < 4; rp++) {
        const int r0 = ty * 8 + 2 * rp;
        float2 c0 = unpack2(acc[rp][0]), c1 = unpack2(acc[rp][1]);
        float2 c2 = unpack2(acc[rp][2]), c3 = unpack2(acc[rp][3]);
        float2 c4 = unpack2(acc[rp][4]), c5 = unpack2(acc[rp][5]);
        float2 c6 = unpack2(acc[rp][6]), c7 = unpack2(acc[rp][7]);
        float4 e0 = make_float4(c0.x, c1.x, c2.x, c3.x);
        float4 o0 = make_float4(c0.y, c1.y, c2.y, c3.y);
        float4 e1 = make_float4(c4.x, c5.x, c6.x, c7.x);
        float4 o1 = make_float4(c4.y, c5.y, c6.y, c7.y);
        *reinterpret_cast<float4*>(C + (size_t)r0 * ldc + tx * 4)             = e0;
        *reinterpret_cast<float4*>(C + (size_t)(r0 + 1) * ldc + tx * 4)       = o0;
        *reinterpret_cast<float4*>(C + (size_t)r0 * ldc + 128 + tx * 4)       = e1;
        *reinterpret_cast<float4*>(C + (size_t)(r0 + 1) * ldc + 128 + tx * 4) = o1;
    }
}

__global__ void __launch_bounds__(128, 4)
gemm_qkv_kernel(const float* __restrict__ x, const float* __restrict__ wq,
                const float* __restrict__ wk, const float* __restrict__ wv)
{
    const int col0 = blockIdx.x << 8;
    const int ks = blockIdx.y;
    const float* W; int ldw, wc0;
    if (col0 < NQ)            { W = wq; ldw = NQ;  wc0 = col0; }
    else if (col0 < NQ + NKV) { W = wk; ldw = NKV; wc0 = col0 - NQ; }
    else                      { W = wv; ldw = NKV; wc0 = col0 - NQ - NKV; }
    gemm_core(x, W, ldw, wc0,
              g_qkv_part + (size_t)ks * B * NTOT + col0, NTOT,
              ks * (4096 / KSQ), (4096 / KSQ) / 16);
}

__global__ void __launch_bounds__(128, 4)
gemm_wo_kernel(const float* __restrict__ wo)
{
    const int col0 = blockIdx.x << 8;
    const int ks = blockIdx.y;
    gemm_core(g_attn, wo, D, col0,
              g_out_part + (size_t)ks * B * D + col0, D,
              ks * (4096 / KSW), (4096 / KSW) / 16);
}

// -------------------- split-K reduce + RoPE --------------------
__global__ void __launch_bounds__(256)
rope_reduce_kernel(const float* __restrict__ fc, const float* __restrict__ fs)
{
    int idx = blockIdx.x * blockDim.x + threadIdx.x;
    int b = idx / (NTOT / 4);
    int col = (idx - b * (NTOT / 4)) * 4;
    const float* p = g_qkv_part + (size_t)b * NTOT + col;
    float4 e = make_float4(0.f, 0.f, 0.f, 0.f);
#pragma unroll
    for (int s = 0; s < KSQ; s++) {
        float4 a = *reinterpret_cast<const float4*>(p + (size_t)s * B * NTOT);
        e.x += a.x; e.y += a.y; e.z += a.z; e.w += a.w;
    }
    if (col < NQ + NKV) {
        int i = (col & (HD - 1)) >> 1;
        float c0 = fc[i], s0 = fs[i];
        float c1 = fc[i + 1], s1 = fs[i + 1];
        float4 r;
        r.x = e.x * c0 - e.y * s0;
        r.y = e.x * s0 + e.y * c0;
        r.z = e.z * c1 - e.w * s1;
        r.w = e.z * s1 + e.w * c1;
        e = r;
    }
    *reinterpret_cast<float4*>(g_qkv + (size_t)b * NTOT + col) = e;
}

// -------------------- attention v2: cp.async smem-staged flash-decode --------
// grid = B*HKV*NSPLIT (1024), 256 thr (8 warps). 4-stage ring of 8 keys;
// commit 3 stages ahead (24 KB in flight/block, no staging registers).
// Warp w consumes key w of each stage via 2 LDS.128; cheap select-reduce.
// Key 2047 (new roped K/V) is redirected in the FILL, not in processing.
__global__ void __launch_bounds__(256, 3)
attn_kernel(const float* __restrict__ cache_k, const float* __restrict__ cache_v)
{
    __shared__ __align__(16) float sbuf[NSTAGE][SKEYS][2][HD];  // 32 KB
    __shared__ float sm_s[8][G];

    const int blk = blockIdx.x;
    const int split = blk & (NSPLIT - 1);
    const int hkv = (blk >> 2) & (HKV - 1);
    const int b = blk >> 5;
    const int tid = threadIdx.x;
    const int w = tid >> 5;
    const int lane = tid & 31;

    const float scale = 0.08838834764831845f;
    unsigned long long q2[G][2];
#pragma unroll
    for (int g = 0; g < G; g++) {
        int h = hkv * G + g;
        float4 q = *reinterpret_cast<const float4*>(
            g_qkv + (size_t)b * NTOT + h * HD + lane * 4);
        q2[g][0] = pack2(q.x * scale, q.y * scale);
        q2[g][1] = pack2(q.z * scale, q.w * scale);
    }

    unsigned long long acc2[G][2];
#pragma unroll
    for (int g = 0; g < G; g++) { acc2[g][0] = 0ull; acc2[g][1] = 0ull; }
    float ssum = 0.f;

    const size_t bh = (size_t)(b * HKV + hkv) * L * HD;
    const float* kb = cache_k + bh;
    const float* vb = cache_v + bh;
    const int key0 = split * (L / NSPLIT);       // 512 keys per block

    // fill mapping: thread t covers 16 B of key (t>>5) at float offset (t&31)*4
    const int fkey = tid >> 5;
    const int foff = (tid & 31) * 4;
    const float* nk = g_qkv + (size_t)b * NTOT + NQ + hkv * HD + foff;
    const float* nv = g_qkv + (size_t)b * NTOT + NQ + NKV + hkv * HD + foff;

#define FILL_STAGE(S)                                                          \
    do {                                                                       \
        int _s = (S);                                                          \
        int _slot = _s & (NSTAGE - 1);                                         \
        int _l = key0 + _s * SKEYS + fkey;                                     \
        const float* _ks = (_l != L - 1) ? kb + (size_t)_l * HD + foff : nk;   \
        const float* _vs = (_l != L - 1) ? vb + (size_t)_l * HD + foff : nv;   \
        __pipeline_memcpy_async(&sbuf[_slot][fkey][0][foff], _ks, 16);         \
        __pipeline_memcpy_async(&sbuf[_slot][fkey][1][foff], _vs, 16);         \
    } while (0)

    FILL_STAGE(0); __pipeline_commit();
    FILL_STAGE(1); __pipeline_commit();
    FILL_STAGE(2); __pipeline_commit();

    const int NIT = (L / NSPLIT) / SKEYS;   // 64
    for (int i = 0; i < NIT; i++) {
        __pipeline_wait_prior(2);           // my group for stage i complete
        __syncthreads();                    // everyone's fills visible; prior reads done
        const int slot = i & (NSTAGE - 1);

        ulonglong2 k2 = *reinterpret_cast<const ulonglong2*>(&sbuf[slot][w][0][lane * 4]);
        ulonglong2 v2 = *reinterpret_cast<const ulonglong2*>(&sbuf[slot][w][1][lane * 4]);

        // dot + cheap select-reduce (1 exp/lane) + packed PV accumulate
        float p[G];
#pragma unroll
        for (int g = 0; g < G; g++) {
            unsigned long long d = mul2(k2.x, q2[g][0]);
            fma2(d, k2.y, q2[g][1]);
            float2 t = unpack2(d);
            p[g] = t.x + t.y;
        }
#pragma unroll
        for (int g = 0; g < G; g++) p[g] += __shfl_xor_sync(0xffffffffu, p[g], 16);
#pragma unroll
        for (int g = 0; g < G; g++) p[g] += __shfl_xor_sync(0xffffffffu, p[g], 8);
        float v = (lane & 16) ? ((lane & 8) ? p[3] : p[2])
                              : ((lane & 8) ? p[1] : p[0]);
        v += __shfl_xor_sync(0xffffffffu, v, 4);
        v += __shfl_xor_sync(0xffffffffu, v, 2);
        v += __shfl_xor_sync(0xffffffffu, v, 1);
        float e = __expf(v);
        ssum += e;
        float e0 = __shfl_sync(0xffffffffu, e, 0);
        float e1 = __shfl_sync(0xffffffffu, e, 8);
        float e2 = __shfl_sync(0xffffffffu, e, 16);
        float e3 = __shfl_sync(0xffffffffu, e, 24);
        unsigned long long d0 = pack2(e0, e0), d1 = pack2(e1, e1);
        unsigned long long d2 = pack2(e2, e2), d3 = pack2(e3, e3);
        fma2(acc2[0][0], d0, v2.x); fma2(acc2[0][1], d0, v2.y);
        fma2(acc2[1][0], d1, v2.x); fma2(acc2[1][1], d1, v2.y);
        fma2(acc2[2][0], d2, v2.x); fma2(acc2[2][1], d2, v2.y);
        fma2(acc2[3][0], d3, v2.x); fma2(acc2[3][1], d3, v2.y);

        if (i + NSTAGE - 1 < NIT) FILL_STAGE(i + NSTAGE - 1);
        __pipeline_commit();                // empty group if drained: keeps count
    }
    __pipeline_wait_prior(0);
    __syncthreads();

    // cross-warp reduce in smem (reuse nothing; small static arrays)
    __shared__ __align__(16) float sm_acc[8][G * HD];
#pragma unroll
    for (int g = 0; g < G; g++) {
        float2 lo = unpack2(acc2[g][0]);
        float2 hi = unpack2(acc2[g][1]);
        float4 o;
        o.x = lo.x; o.y = lo.y; o.z = hi.x; o.w = hi.y;
        *reinterpret_cast<float4*>(&sm_acc[w][g * HD + lane * 4]) = o;
    }
    if ((lane & 7) == 0) sm_s[w][lane >> 3] = ssum;
    __syncthreads();

    for (int e = tid; e < G * HD; e += 256) {
        float vv = 0.f;
#pragma unroll
        for (int ww = 0; ww < 8; ww++) vv += sm_acc[ww][e];
        g_att_part[(size_t)blk * (G * HD) + e] = vv;
    }
    if (tid < G) {
        float vv = 0.f;
#pragma unroll
        for (int ww = 0; ww < 8; ww++) vv += sm_s[ww][tid];
        g_att_s[blk * G + tid] = vv;
    }
#undef FILL_STAGE
}

__global__ void __launch_bounds__(128)
attn_combine_kernel()
{
    const int p = blockIdx.x;
    const int b = p >> 3;
    const int hkv = p & (HKV - 1);
    const int t = threadIdx.x;
    const int g = t >> 5;
    float4 v = make_float4(0.f, 0.f, 0.f, 0.f);
    float s = 0.f;
#pragma unroll
    for (int sp = 0; sp < NSPLIT; sp++) {
        int blk = p * NSPLIT + sp;
        float4 a = *reinterpret_cast<const float4*>(
            g_att_part + (size_t)blk * (G * HD) + t * 4);
        v.x += a.x; v.y += a.y; v.z += a.z; v.w += a.w;
        s += g_att_s[blk * G + g];
    }
    float inv = 1.f / s;
    v.x *= inv; v.y *= inv; v.z *= inv; v.w *= inv;
    *reinterpret_cast<float4*>(g_attn + (size_t)b * NQ + hkv * (G * HD) + t * 4) = v;
}

__global__ void __launch_bounds__(256)
out_reduce_kernel(float* __restrict__ out)
{
    int idx = blockIdx.x * blockDim.x + threadIdx.x;
    float4 v = make_float4(0.f, 0.f, 0.f, 0.f);
#pragma unroll
    for (int s = 0; s < KSW; s++) {
        float4 a = *reinterpret_cast<const float4*>(
            g_out_part + (size_t)s * B * D + idx * 4);
        v.x += a.x; v.y += a.y; v.z += a.z; v.w += a.w;
    }
    *reinterpret_cast<float4*>(out + (size_t)idx * 4) = v;
}

__global__ void pad_kernel() {}

// -------------------- launch (attn at profiled index 3) ----------------------
extern "C" void kernel_launch(void* const* d_in, const int* in_sizes, int n_in,
                              void* d_out, int out_size)
{
    const float* x  = (const float*)d_in[0];
    const float* ck = (const float*)d_in[1];
    const float* cv = (const float*)d_in[2];
    const float* wq = (const float*)d_in[3];
    const float* wk = (const float*)d_in[4];
    const float* wv = (const float*)d_in[5];
    const float* wo = (const float*)d_in[6];
    const float* fc = (const float*)d_in[7];
    const float* fs = (const float*)d_in[8];
    float* out = (float*)d_out;

    pad_kernel<<<1, 32>>>();                                       // idx 0

    dim3 gq(NTOT / 256, KSQ);
    gemm_qkv_kernel<<<gq, 128>>>(x, wq, wk, wv);                   // idx 1

    rope_reduce_kernel<<<(B * NTOT / 4) / 256, 256>>>(fc, fs);     // idx 2

    attn_kernel<<<B * HKV * NSPLIT, 256>>>(ck, cv);                // idx 3 (PROFILED)

    attn_combine_kernel<<<B * HKV, 128>>>();                       // idx 4

    dim3 gw(D / 256, KSW);
    gemm_wo_kernel<<<gw, 128>>>(wo);                               // idx 5

    out_reduce_kernel<<<(B * D / 4) / 256, 256>>>(out);            // idx 6
}

// round 12
// speedup vs baseline: 1.0124x; 1.0124x over previous
#include <cuda_runtime.h>
#include <cuda_pipeline.h>
#include <cstdint>

#define B   32
#define HKV 8
#define G   4
#define HD  128
#define D   4096
#define NQ  4096
#define NKV 1024
#define NTOT 6144
#define L   2048
#define KSQ 16        // split-K for qkv gemm
#define KSW 32        // split-K for wo gemm
#define NSPLIT 4

__device__ float g_qkv_part[KSQ * B * NTOT];
__device__ float g_qkv[B * NTOT];
__device__ float g_att_part[B * HKV * NSPLIT * G * HD];
__device__ float g_att_s[B * HKV * NSPLIT * G];
__device__ float g_attn[B * NQ];
__device__ float g_out_part[KSW * B * D];

// -------------------- f32x2 packed helpers --------------------
__device__ __forceinline__ unsigned long long pack2(float lo, float hi) {
    unsigned long long r;
    asm("mov.b64 %0, {%1, %2};" : "=l"(r) : "f"(lo), "f"(hi));
    return r;
}
__device__ __forceinline__ unsigned long long mul2(unsigned long long a,
                                                   unsigned long long b) {
    unsigned long long r;
    asm("mul.rn.f32x2 %0, %1, %2;" : "=l"(r) : "l"(a), "l"(b));
    return r;
}
__device__ __forceinline__ void fma2(unsigned long long& acc, unsigned long long a,
                                     unsigned long long b) {
    asm("fma.rn.f32x2 %0, %1, %2, %0;" : "+l"(acc) : "l"(a), "l"(b));
}
__device__ __forceinline__ float2 unpack2(unsigned long long v) {
    float2 f;
    asm("mov.b64 {%0, %1}, %2;" : "=f"(f.x), "=f"(f.y) : "l"(v));
    return f;
}
__device__ __forceinline__ unsigned long long dup_lo(unsigned long long v) {
    float2 f = unpack2(v);
    return pack2(f.x, f.x);
}
__device__ __forceinline__ unsigned long long dup_hi(unsigned long long v) {
    float2 f = unpack2(v);
    return pack2(f.y, f.y);
}

// -------------------- GEMM core: 3-stage Ws ring, 1 barrier per k-tile ------
// Ws ring distance 3: fill at iter kt targets slot (kt+2)%3 == (kt-1)%3 whose
// readers finished before the top-of-loop barrier -> single barrier fences
// write->read AND read->write. As is 2-stage (STS at bottom, alternating slot).
#define WS_FLOATS (3 * 16 * 260)
#define GEMM_SMEM ((WS_FLOATS + 2 * 16 * 36) * 4)

__device__ __forceinline__ void gemm_core(
    const float* __restrict__ A,
    const float* __restrict__ W,
    int ldw, int wc0,
    float* __restrict__ C, int ldc,
    int k0, int nkt)
{
    extern __shared__ __align__(16) float smem_dyn[];
    float (*Ws)[16][260] = reinterpret_cast<float (*)[16][260]>(smem_dyn);
    float (*As)[16][36]  = reinterpret_cast<float (*)[16][36]>(smem_dyn + WS_FLOATS);

    const int tid = threadIdx.x;
    const int tx = tid & 31;
    const int ty = tid >> 5;

    const int wr = tid >> 3;
    const int wc = (tid & 7) * 4;
    const int am = tid >> 2;
    const int ak = (tid & 3) * 4;

    unsigned long long acc[4][8];
#pragma unroll
    for (int r = 0; r < 4; r++)
#pragma unroll
        for (int c = 0; c < 8; c++) acc[r][c] = 0ull;

#define FILL_W(SLOT, KG)                                                       \
    do {                                                                       \
        const float* _ws = W + (size_t)((KG) + wr) * ldw + wc0 + wc;           \
        _Pragma("unroll")                                                      \
        for (int j = 0; j < 8; j++)                                            \
            __pipeline_memcpy_async(&Ws[SLOT][wr][wc + j * 32], _ws + j * 32, 16); \
    } while (0)

    // prologue: fill Ws slots 0 and 1 (one group each), store As slot 0
    FILL_W(0, k0);            __pipeline_commit();
    FILL_W(1, k0 + 16);       __pipeline_commit();
    {
        float4 av = *reinterpret_cast<const float4*>(A + am * 4096 + k0 + ak);
        As[0][ak + 0][am] = av.x;
        As[0][ak + 1][am] = av.y;
        As[0][ak + 2][am] = av.z;
        As[0][ak + 3][am] = av.w;
    }

    int ws = 0;        // read slot
    int wf = 2;        // fill slot = (kt+2)%3
    for (int kt = 0; kt < nkt; kt++) {
        __pipeline_wait_prior(1);   // group filling slot ws complete
        __syncthreads();            // fills visible; prior readers of wf done

        if (kt + 2 < nkt) FILL_W(wf, k0 + (kt + 2) * 16);
        __pipeline_commit();        // empty group when drained keeps count

        const int as = kt & 1;
        float4 av2 = make_float4(0.f, 0.f, 0.f, 0.f);
        if (kt + 1 < nkt)
            av2 = *reinterpret_cast<const float4*>(A + am * 4096 + k0 + (kt + 1) * 16 + ak);

#pragma unroll
        for (int k = 0; k < 16; k++) {
            ulonglong2 b01 = *reinterpret_cast<const ulonglong2*>(&Ws[ws][k][tx * 4]);
            ulonglong2 b23 = *reinterpret_cast<const ulonglong2*>(&Ws[ws][k][128 + tx * 4]);
            ulonglong2 ap0 = *reinterpret_cast<const ulonglong2*>(&As[as][k][ty * 8]);
            ulonglong2 ap1 = *reinterpret_cast<const ulonglong2*>(&As[as][k][ty * 8 + 4]);
            unsigned long long d0 = dup_lo(b01.x), d1 = dup_hi(b01.x);
            unsigned long long d2 = dup_lo(b01.y), d3 = dup_hi(b01.y);
            unsigned long long d4 = dup_lo(b23.x), d5 = dup_hi(b23.x);
            unsigned long long d6 = dup_lo(b23.y), d7 = dup_hi(b23.y);
            fma2(acc[0][0], ap0.x, d0); fma2(acc[0][1], ap0.x, d1);
            fma2(acc[0][2], ap0.x, d2); fma2(acc[0][3], ap0.x, d3);
            fma2(acc[0][4], ap0.x, d4); fma2(acc[0][5], ap0.x, d5);
            fma2(acc[0][6], ap0.x, d6); fma2(acc[0][7], ap0.x, d7);
            fma2(acc[1][0], ap0.y, d0); fma2(acc[1][1], ap0.y, d1);
            fma2(acc[1][2], ap0.y, d2); fma2(acc[1][3], ap0.y, d3);
            fma2(acc[1][4], ap0.y, d4); fma2(acc[1][5], ap0.y, d5);
            fma2(acc[1][6], ap0.y, d6); fma2(acc[1][7], ap0.y, d7);
            fma2(acc[2][0], ap1.x, d0); fma2(acc[2][1], ap1.x, d1);
            fma2(acc[2][2], ap1.x, d2); fma2(acc[2][3], ap1.x, d3);
            fma2(acc[2][4], ap1.x, d4); fma2(acc[2][5], ap1.x, d5);
            fma2(acc[2][6], ap1.x, d6); fma2(acc[2][7], ap1.x, d7);
            fma2(acc[3][0], ap1.y, d0); fma2(acc[3][1], ap1.y, d1);
            fma2(acc[3][2], ap1.y, d2); fma2(acc[3][3], ap1.y, d3);
            fma2(acc[3][4], ap1.y, d4); fma2(acc[3][5], ap1.y, d5);
            fma2(acc[3][6], ap1.y, d6); fma2(acc[3][7], ap1.y, d7);
        }

        if (kt + 1 < nkt) {
            const int an = as ^ 1;
            As[an][ak + 0][am] = av2.x;
            As[an][ak + 1][am] = av2.y;
            As[an][ak + 2][am] = av2.z;
            As[an][ak + 3][am] = av2.w;
        }
        ws = (ws == 2) ? 0 : ws + 1;
        wf = (wf == 2) ? 0 : wf + 1;
    }
#undef FILL_W

#pragma unroll
    for (int rp = 0; rp < 4; rp++) {
        const int r0 = ty * 8 + 2 * rp;
        float2 c0 = unpack2(acc[rp][0]), c1 = unpack2(acc[rp][1]);
        float2 c2 = unpack2(acc[rp][2]), c3 = unpack2(acc[rp][3]);
        float2 c4 = unpack2(acc[rp][4]), c5 = unpack2(acc[rp][5]);
        float2 c6 = unpack2(acc[rp][6]), c7 = unpack2(acc[rp][7]);
        float4 e0 = make_float4(c0.x, c1.x, c2.x, c3.x);
        float4 o0 = make_float4(c0.y, c1.y, c2.y, c3.y);
        float4 e1 = make_float4(c4.x, c5.x, c6.x, c7.x);
        float4 o1 = make_float4(c4.y, c5.y, c6.y, c7.y);
        *reinterpret_cast<float4*>(C + (size_t)r0 * ldc + tx * 4)             = e0;
        *reinterpret_cast<float4*>(C + (size_t)(r0 + 1) * ldc + tx * 4)       = o0;
        *reinterpret_cast<float4*>(C + (size_t)r0 * ldc + 128 + tx * 4)       = e1;
        *reinterpret_cast<float4*>(C + (size_t)(r0 + 1) * ldc + 128 + tx * 4) = o1;
    }
}

__global__ void __launch_bounds__(128, 4)
gemm_qkv_kernel(const float* __restrict__ x, const float* __restrict__ wq,
                const float* __restrict__ wk, const float* __restrict__ wv)
{
    const int col0 = blockIdx.x << 8;
    const int ks = blockIdx.y;
    const float* W; int ldw, wc0;
    if (col0 < NQ)            { W = wq; ldw = NQ;  wc0 = col0; }
    else if (col0 < NQ + NKV) { W = wk; ldw = NKV; wc0 = col0 - NQ; }
    else                      { W = wv; ldw = NKV; wc0 = col0 - NQ - NKV; }
    gemm_core(x, W, ldw, wc0,
              g_qkv_part + (size_t)ks * B * NTOT + col0, NTOT,
              ks * (4096 / KSQ), (4096 / KSQ) / 16);
}

__global__ void __launch_bounds__(128, 4)
gemm_wo_kernel(const float* __restrict__ wo)
{
    const int col0 = blockIdx.x << 8;
    const int ks = blockIdx.y;
    gemm_core(g_attn, wo, D, col0,
              g_out_part + (size_t)ks * B * D + col0, D,
              ks * (4096 / KSW), (4096 / KSW) / 16);
}

// -------------------- split-K reduce + RoPE --------------------
__global__ void __launch_bounds__(256)
rope_reduce_kernel(const float* __restrict__ fc, const float* __restrict__ fs)
{
    int idx = blockIdx.x * blockDim.x + threadIdx.x;
    int b = idx / (NTOT / 4);
    int col = (idx - b * (NTOT / 4)) * 4;
    const float* p = g_qkv_part + (size_t)b * NTOT + col;
    float4 e = make_float4(0.f, 0.f, 0.f, 0.f);
#pragma unroll
    for (int s = 0; s < KSQ; s++) {
        float4 a = *reinterpret_cast<const float4*>(p + (size_t)s * B * NTOT);
        e.x += a.x; e.y += a.y; e.z += a.z; e.w += a.w;
    }
    if (col < NQ + NKV) {
        int i = (col & (HD - 1)) >> 1;
        float c0 = fc[i], s0 = fs[i];
        float c1 = fc[i + 1], s1 = fs[i + 1];
        float4 r;
        r.x = e.x * c0 - e.y * s0;
        r.y = e.x * s0 + e.y * c0;
        r.z = e.z * c1 - e.w * s1;
        r.w = e.z * s1 + e.w * c1;
        e = r;
    }
    *reinterpret_cast<float4*>(g_qkv + (size_t)b * NTOT + col) = e;
}

// -------------------- attention: quad-unrolled (R9 best, frozen) ------------
__global__ void __launch_bounds__(256, 2)
attn_kernel(const float* __restrict__ cache_k, const float* __restrict__ cache_v)
{
    const int blk = blockIdx.x;
    const int split = blk & (NSPLIT - 1);
    const int hkv = (blk >> 2) & (HKV - 1);
    const int b = blk >> 5;
    const int tid = threadIdx.x;
    const int w = tid >> 5;
    const int lane = tid & 31;

    const float scale = 0.08838834764831845f;
    unsigned long long q2[G][2];
#pragma unroll
    for (int g = 0; g < G; g++) {
        int h = hkv * G + g;
        float4 q = *reinterpret_cast<const float4*>(
            g_qkv + (size_t)b * NTOT + h * HD + lane * 4);
        q2[g][0] = pack2(q.x * scale, q.y * scale);
        q2[g][1] = pack2(q.z * scale, q.w * scale);
    }

    unsigned long long acc2[G][2];
#pragma unroll
    for (int g = 0; g < G; g++) { acc2[g][0] = 0ull; acc2[g][1] = 0ull; }
    float ssum = 0.f;

    auto process = [&](ulonglong2 k2, ulonglong2 v2) {
        float p[G];
#pragma unroll
        for (int g = 0; g < G; g++) {
            unsigned long long d = mul2(k2.x, q2[g][0]);
            fma2(d, k2.y, q2[g][1]);
            float2 t = unpack2(d);
            p[g] = t.x + t.y;
        }
#pragma unroll
        for (int g = 0; g < G; g++) p[g] += __shfl_xor_sync(0xffffffffu, p[g], 16);
#pragma unroll
        for (int g = 0; g < G; g++) p[g] += __shfl_xor_sync(0xffffffffu, p[g], 8);
        float v = (lane & 16) ? ((lane & 8) ? p[3] : p[2])
                              : ((lane & 8) ? p[1] : p[0]);
        v += __shfl_xor_sync(0xffffffffu, v, 4);
        v += __shfl_xor_sync(0xffffffffu, v, 2);
        v += __shfl_xor_sync(0xffffffffu, v, 1);
        float e = __expf(v);
        ssum += e;
        float e0 = __shfl_sync(0xffffffffu, e, 0);
        float e1 = __shfl_sync(0xffffffffu, e, 8);
        float e2 = __shfl_sync(0xffffffffu, e, 16);
        float e3 = __shfl_sync(0xffffffffu, e, 24);
        unsigned long long d0 = pack2(e0, e0), d1 = pack2(e1, e1);
        unsigned long long d2 = pack2(e2, e2), d3 = pack2(e3, e3);
        fma2(acc2[0][0], d0, v2.x); fma2(acc2[0][1], d0, v2.y);
        fma2(acc2[1][0], d1, v2.x); fma2(acc2[1][1], d1, v2.y);
        fma2(acc2[2][0], d2, v2.x); fma2(acc2[2][1], d2, v2.y);
        fma2(acc2[3][0], d3, v2.x); fma2(acc2[3][1], d3, v2.y);
    };

    const size_t bh = (size_t)(b * HKV + hkv) * L * HD;
    const int base = split * (L / NSPLIT) + w;
    const bool last_warp = (split == NSPLIT - 1) && (w == 7);
    const int niter = last_warp ? 63 : 64;
    const int nquads = niter >> 2;
    const int rem = niter & 3;

    const float* kp = cache_k + bh + (size_t)base * HD + 4 * lane;
    const float* vp = cache_v + bh + (size_t)base * HD + 4 * lane;

    ulonglong2 k0 = *reinterpret_cast<const ulonglong2*>(kp);
    ulonglong2 v0 = *reinterpret_cast<const ulonglong2*>(vp);
    ulonglong2 k1 = *reinterpret_cast<const ulonglong2*>(kp + 8 * HD);
    ulonglong2 v1 = *reinterpret_cast<const ulonglong2*>(vp + 8 * HD);
    ulonglong2 k2 = *reinterpret_cast<const ulonglong2*>(kp + 16 * HD);
    ulonglong2 v2 = *reinterpret_cast<const ulonglong2*>(vp + 16 * HD);
    ulonglong2 k3 = *reinterpret_cast<const ulonglong2*>(kp + 24 * HD);
    ulonglong2 v3 = *reinterpret_cast<const ulonglong2*>(vp + 24 * HD);

    for (int q = 0; q < nquads - 1; q++) {
        kp += 32 * HD;
        vp += 32 * HD;
        ulonglong2 kn0 = *reinterpret_cast<const ulonglong2*>(kp);
        ulonglong2 vn0 = *reinterpret_cast<const ulonglong2*>(vp);
        ulonglong2 kn1 = *reinterpret_cast<const ulonglong2*>(kp + 8 * HD);
        ulonglong2 vn1 = *reinterpret_cast<const ulonglong2*>(vp + 8 * HD);
        ulonglong2 kn2 = *reinterpret_cast<const ulonglong2*>(kp + 16 * HD);
        ulonglong2 vn2 = *reinterpret_cast<const ulonglong2*>(vp + 16 * HD);
        ulonglong2 kn3 = *reinterpret_cast<const ulonglong2*>(kp + 24 * HD);
        ulonglong2 vn3 = *reinterpret_cast<const ulonglong2*>(vp + 24 * HD);
        process(k0, v0);
        process(k1, v1);
        process(k2, v2);
        process(k3, v3);
        k0 = kn0; v0 = vn0; k1 = kn1; v1 = vn1;
        k2 = kn2; v2 = vn2; k3 = kn3; v3 = vn3;
    }
    process(k0, v0);
    process(k1, v1);
    process(k2, v2);
    process(k3, v3);
    kp += 32 * HD;
    vp += 32 * HD;

    for (int r = 0; r < rem; r++) {
        ulonglong2 kr = *reinterpret_cast<const ulonglong2*>(kp + r * 8 * HD);
        ulonglong2 vr = *reinterpret_cast<const ulonglong2*>(vp + r * 8 * HD);
        process(kr, vr);
    }
    if (last_warp) {
        ulonglong2 kr = *reinterpret_cast<const ulonglong2*>(
            g_qkv + (size_t)b * NTOT + NQ + hkv * HD + 4 * lane);
        ulonglong2 vr = *reinterpret_cast<const ulonglong2*>(
            g_qkv + (size_t)b * NTOT + NQ + NKV + hkv * HD + 4 * lane);
        process(kr, vr);
    }

    __shared__ __align__(16) float sm_acc[8][G * HD];
    __shared__ float sm_s[8][G];
#pragma unroll
    for (int g = 0; g < G; g++) {
        float2 lo = unpack2(acc2[g][0]);
        float2 hi = unpack2(acc2[g][1]);
        float4 o;
        o.x = lo.x; o.y = lo.y; o.z = hi.x; o.w = hi.y;
        *reinterpret_cast<float4*>(&sm_acc[w][g * HD + lane * 4]) = o;
    }
    if ((lane & 7) == 0) sm_s[w][lane >> 3] = ssum;
    __syncthreads();

    for (int e = tid; e < G * HD; e += 256) {
        float v = 0.f;
#pragma unroll
        for (int ww = 0; ww < 8; ww++) v += sm_acc[ww][e];
        g_att_part[(size_t)blk * (G * HD) + e] = v;
    }
    if (tid < G) {
        float v = 0.f;
#pragma unroll
        for (int ww = 0; ww < 8; ww++) v += sm_s[ww][tid];
        g_att_s[blk * G + tid] = v;
    }
}

__global__ void __launch_bounds__(128)
attn_combine_kernel()
{
    const int p = blockIdx.x;
    const int b = p >> 3;
    const int hkv = p & (HKV - 1);
    const int t = threadIdx.x;
    const int g = t >> 5;
    float4 v = make_float4(0.f, 0.f, 0.f, 0.f);
    float s = 0.f;
#pragma unroll
    for (int sp = 0; sp < NSPLIT; sp++) {
        int blk = p * NSPLIT + sp;
        float4 a = *reinterpret_cast<const float4*>(
            g_att_part + (size_t)blk * (G * HD) + t * 4);
        v.x += a.x; v.y += a.y; v.z += a.z; v.w += a.w;
        s += g_att_s[blk * G + g];
    }
    float inv = 1.f / s;
    v.x *= inv; v.y *= inv; v.z *= inv; v.w *= inv;
    *reinterpret_cast<float4*>(g_attn + (size_t)b * NQ + hkv * (G * HD) + t * 4) = v;
}

__global__ void __launch_bounds__(256)
out_reduce_kernel(float* __restrict__ out)
{
    int idx = blockIdx.x * blockDim.x + threadIdx.x;
    float4 v = make_float4(0.f, 0.f, 0.f, 0.f);
#pragma unroll
    for (int s = 0; s < KSW; s++) {
        float4 a = *reinterpret_cast<const float4*>(
            g_out_part + (size_t)s * B * D + idx * 4);
        v.x += a.x; v.y += a.y; v.z += a.z; v.w += a.w;
    }
    *reinterpret_cast<float4*>(out + (size_t)idx * 4) = v;
}

__global__ void pad_kernel() {}

// -------------------- launch (gemm_qkv at profiled index 3) ------------------
extern "C" void kernel_launch(void* const* d_in, const int* in_sizes, int n_in,
                              void* d_out, int out_size)
{
    const float* x  = (const float*)d_in[0];
    const float* ck = (const float*)d_in[1];
    const float* cv = (const float*)d_in[2];
    const float* wq = (const float*)d_in[3];
    const float* wk = (const float*)d_in[4];
    const float* wv = (const float*)d_in[5];
    const float* wo = (const float*)d_in[6];
    const float* fc = (const float*)d_in[7];
    const float* fs = (const float*)d_in[8];
    float* out = (float*)d_out;

    // >48KB dynamic smem opt-in (attribute set; not an allocation)
    cudaFuncSetAttribute(gemm_qkv_kernel,
                         cudaFuncAttributeMaxDynamicSharedMemorySize, GEMM_SMEM);
    cudaFuncSetAttribute(gemm_wo_kernel,
                         cudaFuncAttributeMaxDynamicSharedMemorySize, GEMM_SMEM);

    pad_kernel<<<1, 32>>>();                                       // idx 0
    pad_kernel<<<1, 32>>>();                                       // idx 1
    pad_kernel<<<1, 32>>>();                                       // idx 2

    dim3 gq(NTOT / 256, KSQ);
    gemm_qkv_kernel<<<gq, 128, GEMM_SMEM>>>(x, wq, wk, wv);        // idx 3 (PROFILED)

    rope_reduce_kernel<<<(B * NTOT / 4) / 256, 256>>>(fc, fs);     // idx 4

    attn_kernel<<<B * HKV * NSPLIT, 256>>>(ck, cv);                // idx 5

    attn_combine_kernel<<<B * HKV, 128>>>();                       // idx 6

    dim3 gw(D / 256, KSW);
    gemm_wo_kernel<<<gw, 128, GEMM_SMEM>>>(wo);                    // idx 7

    out_reduce_kernel<<<(B * D / 4) / 256, 256>>>(out);            // idx 8
}

// round 13
// speedup vs baseline: 1.0484x; 1.0356x over previous
#include <cuda_runtime.h>
#include <cuda_pipeline.h>
#include <cstdint>

#define B   32
#define HKV 8
#define G   4
#define HD  128
#define D   4096
#define NQ  4096
#define NKV 1024
#define NTOT 6144
#define L   2048
#define KSQ 16        // split-K for qkv gemm
#define KSW 32        // split-K for wo gemm
#define NSPLIT 4

__device__ float g_qkv_part[KSQ * B * NTOT];
__device__ float g_qkv[B * NTOT];
__device__ float g_att_part[B * HKV * NSPLIT * G * HD];
__device__ float g_att_s[B * HKV * NSPLIT * G];
__device__ float g_attn[B * NQ];
__device__ float g_out_part[KSW * B * D];

// -------------------- f32x2 packed helpers --------------------
__device__ __forceinline__ unsigned long long pack2(float lo, float hi) {
    unsigned long long r;
    asm("mov.b64 %0, {%1, %2};" : "=l"(r) : "f"(lo), "f"(hi));
    return r;
}
__device__ __forceinline__ unsigned long long mul2(unsigned long long a,
                                                   unsigned long long b) {
    unsigned long long r;
    asm("mul.rn.f32x2 %0, %1, %2;" : "=l"(r) : "l"(a), "l"(b));
    return r;
}
__device__ __forceinline__ void fma2(unsigned long long& acc, unsigned long long a,
                                     unsigned long long b) {
    asm("fma.rn.f32x2 %0, %1, %2, %0;" : "+l"(acc) : "l"(a), "l"(b));
}
__device__ __forceinline__ float2 unpack2(unsigned long long v) {
    float2 f;
    asm("mov.b64 {%0, %1}, %2;" : "=f"(f.x), "=f"(f.y) : "l"(v));
    return f;
}
__device__ __forceinline__ unsigned long long dup_lo(unsigned long long v) {
    float2 f = unpack2(v);
    return pack2(f.x, f.x);
}
__device__ __forceinline__ unsigned long long dup_hi(unsigned long long v) {
    float2 f = unpack2(v);
    return pack2(f.y, f.y);
}

// -------------------- GEMM core (R9 measured-best config) -------------------
__device__ __forceinline__ void gemm_core(
    const float* __restrict__ A,
    const float* __restrict__ W,
    int ldw, int wc0,
    float* __restrict__ C, int ldc,
    int k0, int nkt)
{
    __shared__ __align__(16) float Ws[2][16][260];
    __shared__ __align__(16) float As[2][16][36];

    const int tid = threadIdx.x;
    const int tx = tid & 31;
    const int ty = tid >> 5;

    const int wr = tid >> 3;
    const int wc = (tid & 7) * 4;
    const int am = tid >> 2;
    const int ak = (tid & 3) * 4;

    unsigned long long acc[4][8];
#pragma unroll
    for (int r = 0; r < 4; r++)
#pragma unroll
        for (int c = 0; c < 8; c++) acc[r][c] = 0ull;

    {
        const float* wsrc = W + (size_t)(k0 + wr) * ldw + wc0 + wc;
#pragma unroll
        for (int j = 0; j < 8; j++)
            __pipeline_memcpy_async(&Ws[0][wr][wc + j * 32], wsrc + j * 32, 16);
        __pipeline_commit();
        float4 av = *reinterpret_cast<const float4*>(A + am * 4096 + k0 + ak);
        As[0][ak + 0][am] = av.x;
        As[0][ak + 1][am] = av.y;
        As[0][ak + 2][am] = av.z;
        As[0][ak + 3][am] = av.w;
    }

    for (int kt = 0; kt < nkt; kt++) {
        const int cur = kt & 1;
        const int nb = cur ^ 1;
        float4 av2 = make_float4(0.f, 0.f, 0.f, 0.f);
        const bool more = (kt + 1 < nkt);
        if (more) {
            const int kg = k0 + (kt + 1) * 16;
            const float* wsrc = W + (size_t)(kg + wr) * ldw + wc0 + wc;
#pragma unroll
            for (int j = 0; j < 8; j++)
                __pipeline_memcpy_async(&Ws[nb][wr][wc + j * 32], wsrc + j * 32, 16);
            __pipeline_commit();
            av2 = *reinterpret_cast<const float4*>(A + am * 4096 + kg + ak);
            __pipeline_wait_prior(1);
        } else {
            __pipeline_wait_prior(0);
        }
        __syncthreads();

#pragma unroll
        for (int k = 0; k < 16; k++) {
            ulonglong2 b01 = *reinterpret_cast<const ulonglong2*>(&Ws[cur][k][tx * 4]);
            ulonglong2 b23 = *reinterpret_cast<const ulonglong2*>(&Ws[cur][k][128 + tx * 4]);
            ulonglong2 ap0 = *reinterpret_cast<const ulonglong2*>(&As[cur][k][ty * 8]);
            ulonglong2 ap1 = *reinterpret_cast<const ulonglong2*>(&As[cur][k][ty * 8 + 4]);
            unsigned long long d0 = dup_lo(b01.x), d1 = dup_hi(b01.x);
            unsigned long long d2 = dup_lo(b01.y), d3 = dup_hi(b01.y);
            unsigned long long d4 = dup_lo(b23.x), d5 = dup_hi(b23.x);
            unsigned long long d6 = dup_lo(b23.y), d7 = dup_hi(b23.y);
            fma2(acc[0][0], ap0.x, d0); fma2(acc[0][1], ap0.x, d1);
            fma2(acc[0][2], ap0.x, d2); fma2(acc[0][3], ap0.x, d3);
            fma2(acc[0][4], ap0.x, d4); fma2(acc[0][5], ap0.x, d5);
            fma2(acc[0][6], ap0.x, d6); fma2(acc[0][7], ap0.x, d7);
            fma2(acc[1][0], ap0.y, d0); fma2(acc[1][1], ap0.y, d1);
            fma2(acc[1][2], ap0.y, d2); fma2(acc[1][3], ap0.y, d3);
            fma2(acc[1][4], ap0.y, d4); fma2(acc[1][5], ap0.y, d5);
            fma2(acc[1][6], ap0.y, d6); fma2(acc[1][7], ap0.y, d7);
            fma2(acc[2][0], ap1.x, d0); fma2(acc[2][1], ap1.x, d1);
            fma2(acc[2][2], ap1.x, d2); fma2(acc[2][3], ap1.x, d3);
            fma2(acc[2][4], ap1.x, d4); fma2(acc[2][5], ap1.x, d5);
            fma2(acc[2][6], ap1.x, d6); fma2(acc[2][7], ap1.x, d7);
            fma2(acc[3][0], ap1.y, d0); fma2(acc[3][1], ap1.y, d1);
            fma2(acc[3][2], ap1.y, d2); fma2(acc[3][3], ap1.y, d3);
            fma2(acc[3][4], ap1.y, d4); fma2(acc[3][5], ap1.y, d5);
            fma2(acc[3][6], ap1.y, d6); fma2(acc[3][7], ap1.y, d7);
        }

        if (more) {
            As[nb][ak + 0][am] = av2.x;
            As[nb][ak + 1][am] = av2.y;
            As[nb][ak + 2][am] = av2.z;
            As[nb][ak + 3][am] = av2.w;
        }
        __syncthreads();
    }

#pragma unroll
    for (int rp = 0; rp < 4; rp++) {
        const int r0 = ty * 8 + 2 * rp;
        float2 c0 = unpack2(acc[rp][0]), c1 = unpack2(acc[rp][1]);
        float2 c2 = unpack2(acc[rp][2]), c3 = unpack2(acc[rp][3]);
        float2 c4 = unpack2(acc[rp][4]), c5 = unpack2(acc[rp][5]);
        float2 c6 = unpack2(acc[rp][6]), c7 = unpack2(acc[rp][7]);
        float4 e0 = make_float4(c0.x, c1.x, c2.x, c3.x);
        float4 o0 = make_float4(c0.y, c1.y, c2.y, c3.y);
        float4 e1 = make_float4(c4.x, c5.x, c6.x, c7.x);
        float4 o1 = make_float4(c4.y, c5.y, c6.y, c7.y);
        *reinterpret_cast<float4*>(C + (size_t)r0 * ldc + tx * 4)             = e0;
        *reinterpret_cast<float4*>(C + (size_t)(r0 + 1) * ldc + tx * 4)       = o0;
        *reinterpret_cast<float4*>(C + (size_t)r0 * ldc + 128 + tx * 4)       = e1;
        *reinterpret_cast<float4*>(C + (size_t)(r0 + 1) * ldc + 128 + tx * 4) = o1;
    }
}

__global__ void __launch_bounds__(128, 4)
gemm_qkv_kernel(const float* __restrict__ x, const float* __restrict__ wq,
                const float* __restrict__ wk, const float* __restrict__ wv)
{
    const int col0 = blockIdx.x << 8;
    const int ks = blockIdx.y;
    const float* W; int ldw, wc0;
    if (col0 < NQ)            { W = wq; ldw = NQ;  wc0 = col0; }
    else if (col0 < NQ + NKV) { W = wk; ldw = NKV; wc0 = col0 - NQ; }
    else                      { W = wv; ldw = NKV; wc0 = col0 - NQ - NKV; }
    gemm_core(x, W, ldw, wc0,
              g_qkv_part + (size_t)ks * B * NTOT + col0, NTOT,
              ks * (4096 / KSQ), (4096 / KSQ) / 16);
}

__global__ void __launch_bounds__(128, 4)
gemm_wo_kernel(const float* __restrict__ wo)
{
    const int col0 = blockIdx.x << 8;
    const int ks = blockIdx.y;
    gemm_core(g_attn, wo, D, col0,
              g_out_part + (size_t)ks * B * D + col0, D,
              ks * (4096 / KSW), (4096 / KSW) / 16);
}

// -------------------- split-K reduce + RoPE --------------------
__global__ void __launch_bounds__(256)
rope_reduce_kernel(const float* __restrict__ fc, const float* __restrict__ fs)
{
    int idx = blockIdx.x * blockDim.x + threadIdx.x;
    int b = idx / (NTOT / 4);
    int col = (idx - b * (NTOT / 4)) * 4;
    const float* p = g_qkv_part + (size_t)b * NTOT + col;
    float4 e = make_float4(0.f, 0.f, 0.f, 0.f);
#pragma unroll
    for (int s = 0; s < KSQ; s++) {
        float4 a = *reinterpret_cast<const float4*>(p + (size_t)s * B * NTOT);
        e.x += a.x; e.y += a.y; e.z += a.z; e.w += a.w;
    }
    if (col < NQ + NKV) {
        int i = (col & (HD - 1)) >> 1;
        float c0 = fc[i], s0 = fs[i];
        float c1 = fc[i + 1], s1 = fs[i + 1];
        float4 r;
        r.x = e.x * c0 - e.y * s0;
        r.y = e.x * s0 + e.y * c0;
        r.z = e.z * c1 - e.w * s1;
        r.w = e.z * s1 + e.w * c1;
        e = r;
    }
    *reinterpret_cast<float4*>(g_qkv + (size_t)b * NTOT + col) = e;
}

// -------------------- attention: quad-unrolled (frozen) ---------------------
__global__ void __launch_bounds__(256, 2)
attn_kernel(const float* __restrict__ cache_k, const float* __restrict__ cache_v)
{
    const int blk = blockIdx.x;
    const int split = blk & (NSPLIT - 1);
    const int hkv = (blk >> 2) & (HKV - 1);
    const int b = blk >> 5;
    const int tid = threadIdx.x;
    const int w = tid >> 5;
    const int lane = tid & 31;

    const float scale = 0.08838834764831845f;
    unsigned long long q2[G][2];
#pragma unroll
    for (int g = 0; g < G; g++) {
        int h = hkv * G + g;
        float4 q = *reinterpret_cast<const float4*>(
            g_qkv + (size_t)b * NTOT + h * HD + lane * 4);
        q2[g][0] = pack2(q.x * scale, q.y * scale);
        q2[g][1] = pack2(q.z * scale, q.w * scale);
    }

    unsigned long long acc2[G][2];
#pragma unroll
    for (int g = 0; g < G; g++) { acc2[g][0] = 0ull; acc2[g][1] = 0ull; }
    float ssum = 0.f;

    auto process = [&](ulonglong2 k2, ulonglong2 v2) {
        float p[G];
#pragma unroll
        for (int g = 0; g < G; g++) {
            unsigned long long d = mul2(k2.x, q2[g][0]);
            fma2(d, k2.y, q2[g][1]);
            float2 t = unpack2(d);
            p[g] = t.x + t.y;
        }
#pragma unroll
        for (int g = 0; g < G; g++) p[g] += __shfl_xor_sync(0xffffffffu, p[g], 16);
#pragma unroll
        for (int g = 0; g < G; g++) p[g] += __shfl_xor_sync(0xffffffffu, p[g], 8);
        float v = (lane & 16) ? ((lane & 8) ? p[3] : p[2])
                              : ((lane & 8) ? p[1] : p[0]);
        v += __shfl_xor_sync(0xffffffffu, v, 4);
        v += __shfl_xor_sync(0xffffffffu, v, 2);
        v += __shfl_xor_sync(0xffffffffu, v, 1);
        float e = __expf(v);
        ssum += e;
        float e0 = __shfl_sync(0xffffffffu, e, 0);
        float e1 = __shfl_sync(0xffffffffu, e, 8);
        float e2 = __shfl_sync(0xffffffffu, e, 16);
        float e3 = __shfl_sync(0xffffffffu, e, 24);
        unsigned long long d0 = pack2(e0, e0), d1 = pack2(e1, e1);
        unsigned long long d2 = pack2(e2, e2), d3 = pack2(e3, e3);
        fma2(acc2[0][0], d0, v2.x); fma2(acc2[0][1], d0, v2.y);
        fma2(acc2[1][0], d1, v2.x); fma2(acc2[1][1], d1, v2.y);
        fma2(acc2[2][0], d2, v2.x); fma2(acc2[2][1], d2, v2.y);
        fma2(acc2[3][0], d3, v2.x); fma2(acc2[3][1], d3, v2.y);
    };

    const size_t bh = (size_t)(b * HKV + hkv) * L * HD;
    const int base = split * (L / NSPLIT) + w;
    const bool last_warp = (split == NSPLIT - 1) && (w == 7);
    const int niter = last_warp ? 63 : 64;
    const int nquads = niter >> 2;
    const int rem = niter & 3;

    const float* kp = cache_k + bh + (size_t)base * HD + 4 * lane;
    const float* vp = cache_v + bh + (size_t)base * HD + 4 * lane;

    ulonglong2 k0 = *reinterpret_cast<const ulonglong2*>(kp);
    ulonglong2 v0 = *reinterpret_cast<const ulonglong2*>(vp);
    ulonglong2 k1 = *reinterpret_cast<const ulonglong2*>(kp + 8 * HD);
    ulonglong2 v1 = *reinterpret_cast<const ulonglong2*>(vp + 8 * HD);
    ulonglong2 k2 = *reinterpret_cast<const ulonglong2*>(kp + 16 * HD);
    ulonglong2 v2 = *reinterpret_cast<const ulonglong2*>(vp + 16 * HD);
    ulonglong2 k3 = *reinterpret_cast<const ulonglong2*>(kp + 24 * HD);
    ulonglong2 v3 = *reinterpret_cast<const ulonglong2*>(vp + 24 * HD);

    for (int q = 0; q < nquads - 1; q++) {
        kp += 32 * HD;
        vp += 32 * HD;
        ulonglong2 kn0 = *reinterpret_cast<const ulonglong2*>(kp);
        ulonglong2 vn0 = *reinterpret_cast<const ulonglong2*>(vp);
        ulonglong2 kn1 = *reinterpret_cast<const ulonglong2*>(kp + 8 * HD);
        ulonglong2 vn1 = *reinterpret_cast<const ulonglong2*>(vp + 8 * HD);
        ulonglong2 kn2 = *reinterpret_cast<const ulonglong2*>(kp + 16 * HD);
        ulonglong2 vn2 = *reinterpret_cast<const ulonglong2*>(vp + 16 * HD);
        ulonglong2 kn3 = *reinterpret_cast<const ulonglong2*>(kp + 24 * HD);
        ulonglong2 vn3 = *reinterpret_cast<const ulonglong2*>(vp + 24 * HD);
        process(k0, v0);
        process(k1, v1);
        process(k2, v2);
        process(k3, v3);
        k0 = kn0; v0 = vn0; k1 = kn1; v1 = vn1;
        k2 = kn2; v2 = vn2; k3 = kn3; v3 = vn3;
    }
    process(k0, v0);
    process(k1, v1);
    process(k2, v2);
    process(k3, v3);
    kp += 32 * HD;
    vp += 32 * HD;

    for (int r = 0; r < rem; r++) {
        ulonglong2 kr = *reinterpret_cast<const ulonglong2*>(kp + r * 8 * HD);
        ulonglong2 vr = *reinterpret_cast<const ulonglong2*>(vp + r * 8 * HD);
        process(kr, vr);
    }
    if (last_warp) {
        ulonglong2 kr = *reinterpret_cast<const ulonglong2*>(
            g_qkv + (size_t)b * NTOT + NQ + hkv * HD + 4 * lane);
        ulonglong2 vr = *reinterpret_cast<const ulonglong2*>(
            g_qkv + (size_t)b * NTOT + NQ + NKV + hkv * HD + 4 * lane);
        process(kr, vr);
    }

    __shared__ __align__(16) float sm_acc[8][G * HD];
    __shared__ float sm_s[8][G];
#pragma unroll
    for (int g = 0; g < G; g++) {
        float2 lo = unpack2(acc2[g][0]);
        float2 hi = unpack2(acc2[g][1]);
        float4 o;
        o.x = lo.x; o.y = lo.y; o.z = hi.x; o.w = hi.y;
        *reinterpret_cast<float4*>(&sm_acc[w][g * HD + lane * 4]) = o;
    }
    if ((lane & 7) == 0) sm_s[w][lane >> 3] = ssum;
    __syncthreads();

    for (int e = tid; e < G * HD; e += 256) {
        float v = 0.f;
#pragma unroll
        for (int ww = 0; ww < 8; ww++) v += sm_acc[ww][e];
        g_att_part[(size_t)blk * (G * HD) + e] = v;
    }
    if (tid < G) {
        float v = 0.f;
#pragma unroll
        for (int ww = 0; ww < 8; ww++) v += sm_s[ww][tid];
        g_att_s[blk * G + tid] = v;
    }
}

__global__ void __launch_bounds__(128)
attn_combine_kernel()
{
    const int p = blockIdx.x;
    const int b = p >> 3;
    const int hkv = p & (HKV - 1);
    const int t = threadIdx.x;
    const int g = t >> 5;
    float4 v = make_float4(0.f, 0.f, 0.f, 0.f);
    float s = 0.f;
#pragma unroll
    for (int sp = 0; sp < NSPLIT; sp++) {
        int blk = p * NSPLIT + sp;
        float4 a = *reinterpret_cast<const float4*>(
            g_att_part + (size_t)blk * (G * HD) + t * 4);
        v.x += a.x; v.y += a.y; v.z += a.z; v.w += a.w;
        s += g_att_s[blk * G + g];
    }
    float inv = 1.f / s;
    v.x *= inv; v.y *= inv; v.z *= inv; v.w *= inv;
    *reinterpret_cast<float4*>(g_attn + (size_t)b * NQ + hkv * (G * HD) + t * 4) = v;
}

__global__ void __launch_bounds__(256)
out_reduce_kernel(float* __restrict__ out)
{
    int idx = blockIdx.x * blockDim.x + threadIdx.x;
    float4 v = make_float4(0.f, 0.f, 0.f, 0.f);
#pragma unroll
    for (int s = 0; s < KSW; s++) {
        float4 a = *reinterpret_cast<const float4*>(
            g_out_part + (size_t)s * B * D + idx * 4);
        v.x += a.x; v.y += a.y; v.z += a.z; v.w += a.w;
    }
    *reinterpret_cast<float4*>(out + (size_t)idx * 4) = v;
}

// -------------------- launch (no pads; consolidation round) ------------------
extern "C" void kernel_launch(void* const* d_in, const int* in_sizes, int n_in,
                              void* d_out, int out_size)
{
    const float* x  = (const float*)d_in[0];
    const float* ck = (const float*)d_in[1];
    const float* cv = (const float*)d_in[2];
    const float* wq = (const float*)d_in[3];
    const float* wk = (const float*)d_in[4];
    const float* wv = (const float*)d_in[5];
    const float* wo = (const float*)d_in[6];
    const float* fc = (const float*)d_in[7];
    const float* fs = (const float*)d_in[8];
    float* out = (float*)d_out;

    dim3 gq(NTOT / 256, KSQ);
    gemm_qkv_kernel<<<gq, 128>>>(x, wq, wk, wv);                   // idx 0

    rope_reduce_kernel<<<(B * NTOT / 4) / 256, 256>>>(fc, fs);     // idx 1

    attn_kernel<<<B * HKV * NSPLIT, 256>>>(ck, cv);                // idx 2

    attn_combine_kernel<<<B * HKV, 128>>>();                       // idx 3 (profiled)

    dim3 gw(D / 256, KSW);
    gemm_wo_kernel<<<gw, 128>>>(wo);                               // idx 4

    out_reduce_kernel<<<(B * D / 4) / 256, 256>>>(out);            // idx 5
}

// round 15
// speedup vs baseline: 1.0843x; 1.0342x over previous
#include <cuda_runtime.h>
#include <cuda_pipeline.h>
#include <cstdint>

#define B   32
#define HKV 8
#define G   4
#define HD  128
#define D   4096
#define NQ  4096
#define NKV 1024
#define NTOT 6144
#define L   2048
#define KSQ 16        // split-K for qkv gemm
#define KSW 32        // split-K for wo gemm

__device__ float g_qkv_part[KSQ * B * NTOT];
__device__ float g_qkv[B * NTOT];
__device__ float g_attn[B * NQ];
__device__ float g_out_part[KSW * B * D];

// -------------------- f32x2 packed helpers --------------------
__device__ __forceinline__ unsigned long long pack2(float lo, float hi) {
    unsigned long long r;
    asm("mov.b64 %0, {%1, %2};" : "=l"(r) : "f"(lo), "f"(hi));
    return r;
}
__device__ __forceinline__ unsigned long long mul2(unsigned long long a,
                                                   unsigned long long b) {
    unsigned long long r;
    asm("mul.rn.f32x2 %0, %1, %2;" : "=l"(r) : "l"(a), "l"(b));
    return r;
}
__device__ __forceinline__ void fma2(unsigned long long& acc, unsigned long long a,
                                     unsigned long long b) {
    asm("fma.rn.f32x2 %0, %1, %2, %0;" : "+l"(acc) : "l"(a), "l"(b));
}
__device__ __forceinline__ float2 unpack2(unsigned long long v) {
    float2 f;
    asm("mov.b64 {%0, %1}, %2;" : "=f"(f.x), "=f"(f.y) : "l"(v));
    return f;
}
__device__ __forceinline__ unsigned long long dup_lo(unsigned long long v) {
    float2 f = unpack2(v);
    return pack2(f.x, f.x);
}
__device__ __forceinline__ unsigned long long dup_hi(unsigned long long v) {
    float2 f = unpack2(v);
    return pack2(f.y, f.y);
}

// -------------------- GEMM core (R9 measured-best config, frozen) ------------
__device__ __forceinline__ void gemm_core(
    const float* __restrict__ A,
    const float* __restrict__ W,
    int ldw, int wc0,
    float* __restrict__ C, int ldc,
    int k0, int nkt)
{
    __shared__ __align__(16) float Ws[2][16][260];
    __shared__ __align__(16) float As[2][16][36];

    const int tid = threadIdx.x;
    const int tx = tid & 31;
    const int ty = tid >> 5;

    const int wr = tid >> 3;
    const int wc = (tid & 7) * 4;
    const int am = tid >> 2;
    const int ak = (tid & 3) * 4;

    unsigned long long acc[4][8];
#pragma unroll
    for (int r = 0; r < 4; r++)
#pragma unroll
        for (int c = 0; c < 8; c++) acc[r][c] = 0ull;

    {
        const float* wsrc = W + (size_t)(k0 + wr) * ldw + wc0 + wc;
#pragma unroll
        for (int j = 0; j < 8; j++)
            __pipeline_memcpy_async(&Ws[0][wr][wc + j * 32], wsrc + j * 32, 16);
        __pipeline_commit();
        float4 av = *reinterpret_cast<const float4*>(A + am * 4096 + k0 + ak);
        As[0][ak + 0][am] = av.x;
        As[0][ak + 1][am] = av.y;
        As[0][ak + 2][am] = av.z;
        As[0][ak + 3][am] = av.w;
    }

    for (int kt = 0; kt < nkt; kt++) {
        const int cur = kt & 1;
        const int nb = cur ^ 1;
        float4 av2 = make_float4(0.f, 0.f, 0.f, 0.f);
        const bool more = (kt + 1 < nkt);
        if (more) {
            const int kg = k0 + (kt + 1) * 16;
            const float* wsrc = W + (size_t)(kg + wr) * ldw + wc0 + wc;
#pragma unroll
            for (int j = 0; j < 8; j++)
                __pipeline_memcpy_async(&Ws[nb][wr][wc + j * 32], wsrc + j * 32, 16);
            __pipeline_commit();
            av2 = *reinterpret_cast<const float4*>(A + am * 4096 + kg + ak);
            __pipeline_wait_prior(1);
        } else {
            __pipeline_wait_prior(0);
        }
        __syncthreads();

#pragma unroll
        for (int k = 0; k < 16; k++) {
            ulonglong2 b01 = *reinterpret_cast<const ulonglong2*>(&Ws[cur][k][tx * 4]);
            ulonglong2 b23 = *reinterpret_cast<const ulonglong2*>(&Ws[cur][k][128 + tx * 4]);
            ulonglong2 ap0 = *reinterpret_cast<const ulonglong2*>(&As[cur][k][ty * 8]);
            ulonglong2 ap1 = *reinterpret_cast<const ulonglong2*>(&As[cur][k][ty * 8 + 4]);
            unsigned long long d0 = dup_lo(b01.x), d1 = dup_hi(b01.x);
            unsigned long long d2 = dup_lo(b01.y), d3 = dup_hi(b01.y);
            unsigned long long d4 = dup_lo(b23.x), d5 = dup_hi(b23.x);
            unsigned long long d6 = dup_lo(b23.y), d7 = dup_hi(b23.y);
            fma2(acc[0][0], ap0.x, d0); fma2(acc[0][1], ap0.x, d1);
            fma2(acc[0][2], ap0.x, d2); fma2(acc[0][3], ap0.x, d3);
            fma2(acc[0][4], ap0.x, d4); fma2(acc[0][5], ap0.x, d5);
            fma2(acc[0][6], ap0.x, d6); fma2(acc[0][7], ap0.x, d7);
            fma2(acc[1][0], ap0.y, d0); fma2(acc[1][1], ap0.y, d1);
            fma2(acc[1][2], ap0.y, d2); fma2(acc[1][3], ap0.y, d3);
            fma2(acc[1][4], ap0.y, d4); fma2(acc[1][5], ap0.y, d5);
            fma2(acc[1][6], ap0.y, d6); fma2(acc[1][7], ap0.y, d7);
            fma2(acc[2][0], ap1.x, d0); fma2(acc[2][1], ap1.x, d1);
            fma2(acc[2][2], ap1.x, d2); fma2(acc[2][3], ap1.x, d3);
            fma2(acc[2][4], ap1.x, d4); fma2(acc[2][5], ap1.x, d5);
            fma2(acc[2][6], ap1.x, d6); fma2(acc[2][7], ap1.x, d7);
            fma2(acc[3][0], ap1.y, d0); fma2(acc[3][1], ap1.y, d1);
            fma2(acc[3][2], ap1.y, d2); fma2(acc[3][3], ap1.y, d3);
            fma2(acc[3][4], ap1.y, d4); fma2(acc[3][5], ap1.y, d5);
            fma2(acc[3][6], ap1.y, d6); fma2(acc[3][7], ap1.y, d7);
        }

        if (more) {
            As[nb][ak + 0][am] = av2.x;
            As[nb][ak + 1][am] = av2.y;
            As[nb][ak + 2][am] = av2.z;
            As[nb][ak + 3][am] = av2.w;
        }
        __syncthreads();
    }

#pragma unroll
    for (int rp = 0; rp < 4; rp++) {
        const int r0 = ty * 8 + 2 * rp;
        float2 c0 = unpack2(acc[rp][0]), c1 = unpack2(acc[rp][1]);
        float2 c2 = unpack2(acc[rp][2]), c3 = unpack2(acc[rp][3]);
        float2 c4 = unpack2(acc[rp][4]), c5 = unpack2(acc[rp][5]);
        float2 c6 = unpack2(acc[rp][6]), c7 = unpack2(acc[rp][7]);
        float4 e0 = make_float4(c0.x, c1.x, c2.x, c3.x);
        float4 o0 = make_float4(c0.y, c1.y, c2.y, c3.y);
        float4 e1 = make_float4(c4.x, c5.x, c6.x, c7.x);
        float4 o1 = make_float4(c4.y, c5.y, c6.y, c7.y);
        *reinterpret_cast<float4*>(C + (size_t)r0 * ldc + tx * 4)             = e0;
        *reinterpret_cast<float4*>(C + (size_t)(r0 + 1) * ldc + tx * 4)       = o0;
        *reinterpret_cast<float4*>(C + (size_t)r0 * ldc + 128 + tx * 4)       = e1;
        *reinterpret_cast<float4*>(C + (size_t)(r0 + 1) * ldc + 128 + tx * 4) = o1;
    }
}

__global__ void __launch_bounds__(128, 4)
gemm_qkv_kernel(const float* __restrict__ x, const float* __restrict__ wq,
                const float* __restrict__ wk, const float* __restrict__ wv)
{
    const int col0 = blockIdx.x << 8;
    const int ks = blockIdx.y;
    const float* W; int ldw, wc0;
    if (col0 < NQ)            { W = wq; ldw = NQ;  wc0 = col0; }
    else if (col0 < NQ + NKV) { W = wk; ldw = NKV; wc0 = col0 - NQ; }
    else                      { W = wv; ldw = NKV; wc0 = col0 - NQ - NKV; }
    gemm_core(x, W, ldw, wc0,
              g_qkv_part + (size_t)ks * B * NTOT + col0, NTOT,
              ks * (4096 / KSQ), (4096 / KSQ) / 16);
}

__global__ void __launch_bounds__(128, 4)
gemm_wo_kernel(const float* __restrict__ wo)
{
    const int col0 = blockIdx.x << 8;
    const int ks = blockIdx.y;
    gemm_core(g_attn, wo, D, col0,
              g_out_part + (size_t)ks * B * D + col0, D,
              ks * (4096 / KSW), (4096 / KSW) / 16);
}

// -------------------- split-K reduce + RoPE --------------------
__global__ void __launch_bounds__(256)
rope_reduce_kernel(const float* __restrict__ fc, const float* __restrict__ fs)
{
    int idx = blockIdx.x * blockDim.x + threadIdx.x;
    int b = idx / (NTOT / 4);
    int col = (idx - b * (NTOT / 4)) * 4;
    const float* p = g_qkv_part + (size_t)b * NTOT + col;
    float4 e = make_float4(0.f, 0.f, 0.f, 0.f);
#pragma unroll
    for (int s = 0; s < KSQ; s++) {
        float4 a = *reinterpret_cast<const float4*>(p + (size_t)s * B * NTOT);
        e.x += a.x; e.y += a.y; e.z += a.z; e.w += a.w;
    }
    if (col < NQ + NKV) {
        int i = (col & (HD - 1)) >> 1;
        float c0 = fc[i], s0 = fs[i];
        float c1 = fc[i + 1], s1 = fs[i + 1];
        float4 r;
        r.x = e.x * c0 - e.y * s0;
        r.y = e.x * s0 + e.y * c0;
        r.z = e.z * c1 - e.w * s1;
        r.w = e.z * s1 + e.w * c1;
        e = r;
    }
    *reinterpret_cast<float4*>(g_qkv + (size_t)b * NTOT + col) = e;
}

// -------------------- attention: single-wave, no splits ----------------------
// grid = B*HKV (256 <= 296 concurrent at 2 blocks/SM): ONE wave, no tail.
// Block owns a full (b,hkv): 8 warps x 256 keys, quad-unrolled depth-1 prefetch.
// Normalizes in-block and writes g_attn directly. Epilogue uses threads 0..127
// only (512 output floats = 128 float4s) — R14 bug was running it on all 256.
__global__ void __launch_bounds__(256, 2)
attn_kernel(const float* __restrict__ cache_k, const float* __restrict__ cache_v)
{
    const int blk = blockIdx.x;          // b*HKV + hkv
    const int hkv = blk & (HKV - 1);
    const int b = blk >> 3;
    const int tid = threadIdx.x;
    const int w = tid >> 5;
    const int lane = tid & 31;

    const float scale = 0.08838834764831845f;
    unsigned long long q2[G][2];
#pragma unroll
    for (int g = 0; g < G; g++) {
        int h = hkv * G + g;
        float4 q = *reinterpret_cast<const float4*>(
            g_qkv + (size_t)b * NTOT + h * HD + lane * 4);
        q2[g][0] = pack2(q.x * scale, q.y * scale);
        q2[g][1] = pack2(q.z * scale, q.w * scale);
    }

    unsigned long long acc2[G][2];
#pragma unroll
    for (int g = 0; g < G; g++) { acc2[g][0] = 0ull; acc2[g][1] = 0ull; }
    float ssum = 0.f;

    auto process = [&](ulonglong2 k2, ulonglong2 v2) {
        float p[G];
#pragma unroll
        for (int g = 0; g < G; g++) {
            unsigned long long d = mul2(k2.x, q2[g][0]);
            fma2(d, k2.y, q2[g][1]);
            float2 t = unpack2(d);
            p[g] = t.x + t.y;
        }
#pragma unroll
        for (int g = 0; g < G; g++) p[g] += __shfl_xor_sync(0xffffffffu, p[g], 16);
#pragma unroll
        for (int g = 0; g < G; g++) p[g] += __shfl_xor_sync(0xffffffffu, p[g], 8);
        float v = (lane & 16) ? ((lane & 8) ? p[3] : p[2])
                              : ((lane & 8) ? p[1] : p[0]);
        v += __shfl_xor_sync(0xffffffffu, v, 4);
        v += __shfl_xor_sync(0xffffffffu, v, 2);
        v += __shfl_xor_sync(0xffffffffu, v, 1);
        float e = __expf(v);
        ssum += e;
        float e0 = __shfl_sync(0xffffffffu, e, 0);
        float e1 = __shfl_sync(0xffffffffu, e, 8);
        float e2 = __shfl_sync(0xffffffffu, e, 16);
        float e3 = __shfl_sync(0xffffffffu, e, 24);
        unsigned long long d0 = pack2(e0, e0), d1 = pack2(e1, e1);
        unsigned long long d2 = pack2(e2, e2), d3 = pack2(e3, e3);
        fma2(acc2[0][0], d0, v2.x); fma2(acc2[0][1], d0, v2.y);
        fma2(acc2[1][0], d1, v2.x); fma2(acc2[1][1], d1, v2.y);
        fma2(acc2[2][0], d2, v2.x); fma2(acc2[2][1], d2, v2.y);
        fma2(acc2[3][0], d3, v2.x); fma2(acc2[3][1], d3, v2.y);
    };

    const size_t bh = (size_t)(b * HKV + hkv) * L * HD;
    const bool last_warp = (w == 7);
    const int niter = last_warp ? (L / 8 - 1) : (L / 8);   // 255 or 256 keys
    const int nquads = niter >> 2;                         // 63 or 64
    const int rem = niter & 3;                             // 3 or 0

    const float* kp = cache_k + bh + (size_t)w * HD + 4 * lane;
    const float* vp = cache_v + bh + (size_t)w * HD + 4 * lane;

    ulonglong2 k0 = *reinterpret_cast<const ulonglong2*>(kp);
    ulonglong2 v0 = *reinterpret_cast<const ulonglong2*>(vp);
    ulonglong2 k1 = *reinterpret_cast<const ulonglong2*>(kp + 8 * HD);
    ulonglong2 v1 = *reinterpret_cast<const ulonglong2*>(vp + 8 * HD);
    ulonglong2 k2 = *reinterpret_cast<const ulonglong2*>(kp + 16 * HD);
    ulonglong2 v2 = *reinterpret_cast<const ulonglong2*>(vp + 16 * HD);
    ulonglong2 k3 = *reinterpret_cast<const ulonglong2*>(kp + 24 * HD);
    ulonglong2 v3 = *reinterpret_cast<const ulonglong2*>(vp + 24 * HD);

    for (int q = 0; q < nquads - 1; q++) {
        kp += 32 * HD;
        vp += 32 * HD;
        ulonglong2 kn0 = *reinterpret_cast<const ulonglong2*>(kp);
        ulonglong2 vn0 = *reinterpret_cast<const ulonglong2*>(vp);
        ulonglong2 kn1 = *reinterpret_cast<const ulonglong2*>(kp + 8 * HD);
        ulonglong2 vn1 = *reinterpret_cast<const ulonglong2*>(vp + 8 * HD);
        ulonglong2 kn2 = *reinterpret_cast<const ulonglong2*>(kp + 16 * HD);
        ulonglong2 vn2 = *reinterpret_cast<const ulonglong2*>(vp + 16 * HD);
        ulonglong2 kn3 = *reinterpret_cast<const ulonglong2*>(kp + 24 * HD);
        ulonglong2 vn3 = *reinterpret_cast<const ulonglong2*>(vp + 24 * HD);
        process(k0, v0);
        process(k1, v1);
        process(k2, v2);
        process(k3, v3);
        k0 = kn0; v0 = vn0; k1 = kn1; v1 = vn1;
        k2 = kn2; v2 = vn2; k3 = kn3; v3 = vn3;
    }
    process(k0, v0);
    process(k1, v1);
    process(k2, v2);
    process(k3, v3);
    kp += 32 * HD;
    vp += 32 * HD;

    for (int r = 0; r < rem; r++) {
        ulonglong2 kr = *reinterpret_cast<const ulonglong2*>(kp + r * 8 * HD);
        ulonglong2 vr = *reinterpret_cast<const ulonglong2*>(vp + r * 8 * HD);
        process(kr, vr);
    }
    if (last_warp) {   // key 2047 = new roped K/V
        ulonglong2 kr = *reinterpret_cast<const ulonglong2*>(
            g_qkv + (size_t)b * NTOT + NQ + hkv * HD + 4 * lane);
        ulonglong2 vr = *reinterpret_cast<const ulonglong2*>(
            g_qkv + (size_t)b * NTOT + NQ + NKV + hkv * HD + 4 * lane);
        process(kr, vr);
    }

    // cross-warp reduce + normalize + direct write to g_attn
    __shared__ __align__(16) float sm_acc[8][G * HD];
    __shared__ float sm_s[8][G];
#pragma unroll
    for (int g = 0; g < G; g++) {
        float2 lo = unpack2(acc2[g][0]);
        float2 hi = unpack2(acc2[g][1]);
        float4 o;
        o.x = lo.x; o.y = lo.y; o.z = hi.x; o.w = hi.y;
        *reinterpret_cast<float4*>(&sm_acc[w][g * HD + lane * 4]) = o;
    }
    if ((lane & 7) == 0) sm_s[w][lane >> 3] = ssum;
    __syncthreads();

    // 512 output floats = 128 float4s: threads 0..127 only (t>>5 = g in 0..3)
    if (tid < 128) {
        const int t = tid;
        const int g = t >> 5;
        float s = 0.f;
#pragma unroll
        for (int ww = 0; ww < 8; ww++) s += sm_s[ww][g];
        float4 v = make_float4(0.f, 0.f, 0.f, 0.f);
#pragma unroll
        for (int ww = 0; ww < 8; ww++) {
            float4 a = *reinterpret_cast<const float4*>(&sm_acc[ww][t * 4]);
            v.x += a.x; v.y += a.y; v.z += a.z; v.w += a.w;
        }
        float inv = 1.f / s;
        v.x *= inv; v.y *= inv; v.z *= inv; v.w *= inv;
        *reinterpret_cast<float4*>(
            g_attn + (size_t)b * NQ + hkv * (G * HD) + t * 4) = v;
    }
}

__global__ void __launch_bounds__(256)
out_reduce_kernel(float* __restrict__ out)
{
    int idx = blockIdx.x * blockDim.x + threadIdx.x;
    float4 v = make_float4(0.f, 0.f, 0.f, 0.f);
#pragma unroll
    for (int s = 0; s < KSW; s++) {
        float4 a = *reinterpret_cast<const float4*>(
            g_out_part + (size_t)s * B * D + idx * 4);
        v.x += a.x; v.y += a.y; v.z += a.z; v.w += a.w;
    }
    *reinterpret_cast<float4*>(out + (size_t)idx * 4) = v;
}

// -------------------- launch (gemm_wo at profiled index 3) -------------------
extern "C" void kernel_launch(void* const* d_in, const int* in_sizes, int n_in,
                              void* d_out, int out_size)
{
    const float* x  = (const float*)d_in[0];
    const float* ck = (const float*)d_in[1];
    const float* cv = (const float*)d_in[2];
    const float* wq = (const float*)d_in[3];
    const float* wk = (const float*)d_in[4];
    const float* wv = (const float*)d_in[5];
    const float* wo = (const float*)d_in[6];
    const float* fc = (const float*)d_in[7];
    const float* fs = (const float*)d_in[8];
    float* out = (float*)d_out;

    dim3 gq(NTOT / 256, KSQ);
    gemm_qkv_kernel<<<gq, 128>>>(x, wq, wk, wv);                   // idx 0

    rope_reduce_kernel<<<(B * NTOT / 4) / 256, 256>>>(fc, fs);     // idx 1

    attn_kernel<<<B * HKV, 256>>>(ck, cv);                         // idx 2

    dim3 gw(D / 256, KSW);
    gemm_wo_kernel<<<gw, 128>>>(wo);                               // idx 3 (profiled)

    out_reduce_kernel<<<(B * D / 4) / 256, 256>>>(out);            // idx 4
}

// round 16
// speedup vs baseline: 1.1152x; 1.0285x over previous
#include <cuda_runtime.h>
#include <cuda_pipeline.h>
#include <cstdint>

#define B   32
#define HKV 8
#define G   4
#define HD  128
#define D   4096
#define NQ  4096
#define NKV 1024
#define NTOT 6144
#define L   2048
#define KSQ 16        // split-K for qkv gemm
#define KSW 32        // split-K for wo gemm

__device__ float g_qkv_part[KSQ * B * NTOT];
__device__ float g_attn[B * NQ];
__device__ float g_out_part[KSW * B * D];

// -------------------- f32x2 packed helpers --------------------
__device__ __forceinline__ unsigned long long pack2(float lo, float hi) {
    unsigned long long r;
    asm("mov.b64 %0, {%1, %2};" : "=l"(r) : "f"(lo), "f"(hi));
    return r;
}
__device__ __forceinline__ unsigned long long mul2(unsigned long long a,
                                                   unsigned long long b) {
    unsigned long long r;
    asm("mul.rn.f32x2 %0, %1, %2;" : "=l"(r) : "l"(a), "l"(b));
    return r;
}
__device__ __forceinline__ void fma2(unsigned long long& acc, unsigned long long a,
                                     unsigned long long b) {
    asm("fma.rn.f32x2 %0, %1, %2, %0;" : "+l"(acc) : "l"(a), "l"(b));
}
__device__ __forceinline__ float2 unpack2(unsigned long long v) {
    float2 f;
    asm("mov.b64 {%0, %1}, %2;" : "=f"(f.x), "=f"(f.y) : "l"(v));
    return f;
}
__device__ __forceinline__ unsigned long long dup_lo(unsigned long long v) {
    float2 f = unpack2(v);
    return pack2(f.x, f.x);
}
__device__ __forceinline__ unsigned long long dup_hi(unsigned long long v) {
    float2 f = unpack2(v);
    return pack2(f.y, f.y);
}

// -------------------- GEMM core (R9 measured-best config, frozen) ------------
__device__ __forceinline__ void gemm_core(
    const float* __restrict__ A,
    const float* __restrict__ W,
    int ldw, int wc0,
    float* __restrict__ C, int ldc,
    int k0, int nkt)
{
    __shared__ __align__(16) float Ws[2][16][260];
    __shared__ __align__(16) float As[2][16][36];

    const int tid = threadIdx.x;
    const int tx = tid & 31;
    const int ty = tid >> 5;

    const int wr = tid >> 3;
    const int wc = (tid & 7) * 4;
    const int am = tid >> 2;
    const int ak = (tid & 3) * 4;

    unsigned long long acc[4][8];
#pragma unroll
    for (int r = 0; r < 4; r++)
#pragma unroll
        for (int c = 0; c < 8; c++) acc[r][c] = 0ull;

    {
        const float* wsrc = W + (size_t)(k0 + wr) * ldw + wc0 + wc;
#pragma unroll
        for (int j = 0; j < 8; j++)
            __pipeline_memcpy_async(&Ws[0][wr][wc + j * 32], wsrc + j * 32, 16);
        __pipeline_commit();
        float4 av = *reinterpret_cast<const float4*>(A + am * 4096 + k0 + ak);
        As[0][ak + 0][am] = av.x;
        As[0][ak + 1][am] = av.y;
        As[0][ak + 2][am] = av.z;
        As[0][ak + 3][am] = av.w;
    }

    for (int kt = 0; kt < nkt; kt++) {
        const int cur = kt & 1;
        const int nb = cur ^ 1;
        float4 av2 = make_float4(0.f, 0.f, 0.f, 0.f);
        const bool more = (kt + 1 < nkt);
        if (more) {
            const int kg = k0 + (kt + 1) * 16;
            const float* wsrc = W + (size_t)(kg + wr) * ldw + wc0 + wc;
#pragma unroll
            for (int j = 0; j < 8; j++)
                __pipeline_memcpy_async(&Ws[nb][wr][wc + j * 32], wsrc + j * 32, 16);
            __pipeline_commit();
            av2 = *reinterpret_cast<const float4*>(A + am * 4096 + kg + ak);
            __pipeline_wait_prior(1);
        } else {
            __pipeline_wait_prior(0);
        }
        __syncthreads();

#pragma unroll
        for (int k = 0; k < 16; k++) {
            ulonglong2 b01 = *reinterpret_cast<const ulonglong2*>(&Ws[cur][k][tx * 4]);
            ulonglong2 b23 = *reinterpret_cast<const ulonglong2*>(&Ws[cur][k][128 + tx * 4]);
            ulonglong2 ap0 = *reinterpret_cast<const ulonglong2*>(&As[cur][k][ty * 8]);
            ulonglong2 ap1 = *reinterpret_cast<const ulonglong2*>(&As[cur][k][ty * 8 + 4]);
            unsigned long long d0 = dup_lo(b01.x), d1 = dup_hi(b01.x);
            unsigned long long d2 = dup_lo(b01.y), d3 = dup_hi(b01.y);
            unsigned long long d4 = dup_lo(b23.x), d5 = dup_hi(b23.x);
            unsigned long long d6 = dup_lo(b23.y), d7 = dup_hi(b23.y);
            fma2(acc[0][0], ap0.x, d0); fma2(acc[0][1], ap0.x, d1);
            fma2(acc[0][2], ap0.x, d2); fma2(acc[0][3], ap0.x, d3);
            fma2(acc[0][4], ap0.x, d4); fma2(acc[0][5], ap0.x, d5);
            fma2(acc[0][6], ap0.x, d6); fma2(acc[0][7], ap0.x, d7);
            fma2(acc[1][0], ap0.y, d0); fma2(acc[1][1], ap0.y, d1);
            fma2(acc[1][2], ap0.y, d2); fma2(acc[1][3], ap0.y, d3);
            fma2(acc[1][4], ap0.y, d4); fma2(acc[1][5], ap0.y, d5);
            fma2(acc[1][6], ap0.y, d6); fma2(acc[1][7], ap0.y, d7);
            fma2(acc[2][0], ap1.x, d0); fma2(acc[2][1], ap1.x, d1);
            fma2(acc[2][2], ap1.x, d2); fma2(acc[2][3], ap1.x, d3);
            fma2(acc[2][4], ap1.x, d4); fma2(acc[2][5], ap1.x, d5);
            fma2(acc[2][6], ap1.x, d6); fma2(acc[2][7], ap1.x, d7);
            fma2(acc[3][0], ap1.y, d0); fma2(acc[3][1], ap1.y, d1);
            fma2(acc[3][2], ap1.y, d2); fma2(acc[3][3], ap1.y, d3);
            fma2(acc[3][4], ap1.y, d4); fma2(acc[3][5], ap1.y, d5);
            fma2(acc[3][6], ap1.y, d6); fma2(acc[3][7], ap1.y, d7);
        }

        if (more) {
            As[nb][ak + 0][am] = av2.x;
            As[nb][ak + 1][am] = av2.y;
            As[nb][ak + 2][am] = av2.z;
            As[nb][ak + 3][am] = av2.w;
        }
        __syncthreads();
    }

#pragma unroll
    for (int rp = 0; rp < 4; rp++) {
        const int r0 = ty * 8 + 2 * rp;
        float2 c0 = unpack2(acc[rp][0]), c1 = unpack2(acc[rp][1]);
        float2 c2 = unpack2(acc[rp][2]), c3 = unpack2(acc[rp][3]);
        float2 c4 = unpack2(acc[rp][4]), c5 = unpack2(acc[rp][5]);
        float2 c6 = unpack2(acc[rp][6]), c7 = unpack2(acc[rp][7]);
        float4 e0 = make_float4(c0.x, c1.x, c2.x, c3.x);
        float4 o0 = make_float4(c0.y, c1.y, c2.y, c3.y);
        float4 e1 = make_float4(c4.x, c5.x, c6.x, c7.x);
        float4 o1 = make_float4(c4.y, c5.y, c6.y, c7.y);
        *reinterpret_cast<float4*>(C + (size_t)r0 * ldc + tx * 4)             = e0;
        *reinterpret_cast<float4*>(C + (size_t)(r0 + 1) * ldc + tx * 4)       = o0;
        *reinterpret_cast<float4*>(C + (size_t)r0 * ldc + 128 + tx * 4)       = e1;
        *reinterpret_cast<float4*>(C + (size_t)(r0 + 1) * ldc + 128 + tx * 4) = o1;
    }
}

__global__ void __launch_bounds__(128, 4)
gemm_qkv_kernel(const float* __restrict__ x, const float* __restrict__ wq,
                const float* __restrict__ wk, const float* __restrict__ wv)
{
    const int col0 = blockIdx.x << 8;
    const int ks = blockIdx.y;
    const float* W; int ldw, wc0;
    if (col0 < NQ)            { W = wq; ldw = NQ;  wc0 = col0; }
    else if (col0 < NQ + NKV) { W = wk; ldw = NKV; wc0 = col0 - NQ; }
    else                      { W = wv; ldw = NKV; wc0 = col0 - NQ - NKV; }
    gemm_core(x, W, ldw, wc0,
              g_qkv_part + (size_t)ks * B * NTOT + col0, NTOT,
              ks * (4096 / KSQ), (4096 / KSQ) / 16);
}

__global__ void __launch_bounds__(128, 4)
gemm_wo_kernel(const float* __restrict__ wo)
{
    const int col0 = blockIdx.x << 8;
    const int ks = blockIdx.y;
    gemm_core(g_attn, wo, D, col0,
              g_out_part + (size_t)ks * B * D + col0, D,
              ks * (4096 / KSW), (4096 / KSW) / 16);
}

// -------------------- attention: single-wave + fused rope/reduce -------------
// grid = B*HKV (256): ONE wave. Prologue reduces the KSQ qkv partials for this
// block's own q-heads + k/v head, applies RoPE, stages in smem. rope_reduce
// kernel and g_qkv buffer are eliminated.
__global__ void __launch_bounds__(256, 2)
attn_kernel(const float* __restrict__ cache_k, const float* __restrict__ cache_v,
            const float* __restrict__ fc, const float* __restrict__ fs)
{
    __shared__ __align__(16) float sq[G * HD];   // roped q, 4 heads
    __shared__ __align__(16) float sk[HD];       // roped new k (pos 2047)
    __shared__ __align__(16) float sv[HD];       // new v

    const int blk = blockIdx.x;          // b*HKV + hkv
    const int hkv = blk & (HKV - 1);
    const int b = blk >> 3;
    const int tid = threadIdx.x;
    const int w = tid >> 5;
    const int lane = tid & 31;

    // ---- fused split-K reduce + RoPE for this block's slice (384 pairs) ----
    for (int p = tid; p < 384; p += 256) {
        int col;
        bool dorope = true;
        if (p < 256)        col = hkv * (G * HD) + 2 * p;                 // q
        else if (p < 320)   col = NQ + hkv * HD + 2 * (p - 256);          // k
        else {              col = NQ + NKV + hkv * HD + 2 * (p - 320);    // v
                            dorope = false; }
        const float* src = g_qkv_part + (size_t)b * NTOT + col;
        float e0 = 0.f, e1 = 0.f;
#pragma unroll
        for (int s = 0; s < KSQ; s++) {
            float2 a = *reinterpret_cast<const float2*>(src + (size_t)s * B * NTOT);
            e0 += a.x; e1 += a.y;
        }
        if (dorope) {
            int i = (col & (HD - 1)) >> 1;
            float c = fc[i], sn = fs[i];
            float r0 = e0 * c - e1 * sn;
            float r1 = e0 * sn + e1 * c;
            e0 = r0; e1 = r1;
        }
        if (p < 256)      { sq[2 * p] = e0;             sq[2 * p + 1] = e1; }
        else if (p < 320) { sk[2 * (p - 256)] = e0;     sk[2 * (p - 256) + 1] = e1; }
        else              { sv[2 * (p - 320)] = e0;     sv[2 * (p - 320) + 1] = e1; }
    }
    __syncthreads();

    const float scale = 0.08838834764831845f;
    unsigned long long q2[G][2];
#pragma unroll
    for (int g = 0; g < G; g++) {
        float4 q = *reinterpret_cast<const float4*>(sq + g * HD + lane * 4);
        q2[g][0] = pack2(q.x * scale, q.y * scale);
        q2[g][1] = pack2(q.z * scale, q.w * scale);
    }

    unsigned long long acc2[G][2];
#pragma unroll
    for (int g = 0; g < G; g++) { acc2[g][0] = 0ull; acc2[g][1] = 0ull; }
    float ssum = 0.f;

    auto process = [&](ulonglong2 k2, ulonglong2 v2) {
        float p[G];
#pragma unroll
        for (int g = 0; g < G; g++) {
            unsigned long long d = mul2(k2.x, q2[g][0]);
            fma2(d, k2.y, q2[g][1]);
            float2 t = unpack2(d);
            p[g] = t.x + t.y;
        }
#pragma unroll
        for (int g = 0; g < G; g++) p[g] += __shfl_xor_sync(0xffffffffu, p[g], 16);
#pragma unroll
        for (int g = 0; g < G; g++) p[g] += __shfl_xor_sync(0xffffffffu, p[g], 8);
        float v = (lane & 16) ? ((lane & 8) ? p[3] : p[2])
                              : ((lane & 8) ? p[1] : p[0]);
        v += __shfl_xor_sync(0xffffffffu, v, 4);
        v += __shfl_xor_sync(0xffffffffu, v, 2);
        v += __shfl_xor_sync(0xffffffffu, v, 1);
        float e = __expf(v);
        ssum += e;
        float e0 = __shfl_sync(0xffffffffu, e, 0);
        float e1 = __shfl_sync(0xffffffffu, e, 8);
        float e2 = __shfl_sync(0xffffffffu, e, 16);
        float e3 = __shfl_sync(0xffffffffu, e, 24);
        unsigned long long d0 = pack2(e0, e0), d1 = pack2(e1, e1);
        unsigned long long d2 = pack2(e2, e2), d3 = pack2(e3, e3);
        fma2(acc2[0][0], d0, v2.x); fma2(acc2[0][1], d0, v2.y);
        fma2(acc2[1][0], d1, v2.x); fma2(acc2[1][1], d1, v2.y);
        fma2(acc2[2][0], d2, v2.x); fma2(acc2[2][1], d2, v2.y);
        fma2(acc2[3][0], d3, v2.x); fma2(acc2[3][1], d3, v2.y);
    };

    const size_t bh = (size_t)(b * HKV + hkv) * L * HD;
    const bool last_warp = (w == 7);
    const int niter = last_warp ? (L / 8 - 1) : (L / 8);   // 255 or 256 keys
    const int nquads = niter >> 2;                         // 63 or 64
    const int rem = niter & 3;                             // 3 or 0

    const float* kp = cache_k + bh + (size_t)w * HD + 4 * lane;
    const float* vp = cache_v + bh + (size_t)w * HD + 4 * lane;

    ulonglong2 k0 = *reinterpret_cast<const ulonglong2*>(kp);
    ulonglong2 v0 = *reinterpret_cast<const ulonglong2*>(vp);
    ulonglong2 k1 = *reinterpret_cast<const ulonglong2*>(kp + 8 * HD);
    ulonglong2 v1 = *reinterpret_cast<const ulonglong2*>(vp + 8 * HD);
    ulonglong2 k2 = *reinterpret_cast<const ulonglong2*>(kp + 16 * HD);
    ulonglong2 v2 = *reinterpret_cast<const ulonglong2*>(vp + 16 * HD);
    ulonglong2 k3 = *reinterpret_cast<const ulonglong2*>(kp + 24 * HD);
    ulonglong2 v3 = *reinterpret_cast<const ulonglong2*>(vp + 24 * HD);

    for (int q = 0; q < nquads - 1; q++) {
        kp += 32 * HD;
        vp += 32 * HD;
        ulonglong2 kn0 = *reinterpret_cast<const ulonglong2*>(kp);
        ulonglong2 vn0 = *reinterpret_cast<const ulonglong2*>(vp);
        ulonglong2 kn1 = *reinterpret_cast<const ulonglong2*>(kp + 8 * HD);
        ulonglong2 vn1 = *reinterpret_cast<const ulonglong2*>(vp + 8 * HD);
        ulonglong2 kn2 = *reinterpret_cast<const ulonglong2*>(kp + 16 * HD);
        ulonglong2 vn2 = *reinterpret_cast<const ulonglong2*>(vp + 16 * HD);
        ulonglong2 kn3 = *reinterpret_cast<const ulonglong2*>(kp + 24 * HD);
        ulonglong2 vn3 = *reinterpret_cast<const ulonglong2*>(vp + 24 * HD);
        process(k0, v0);
        process(k1, v1);
        process(k2, v2);
        process(k3, v3);
        k0 = kn0; v0 = vn0; k1 = kn1; v1 = vn1;
        k2 = kn2; v2 = vn2; k3 = kn3; v3 = vn3;
    }
    process(k0, v0);
    process(k1, v1);
    process(k2, v2);
    process(k3, v3);
    kp += 32 * HD;
    vp += 32 * HD;

    for (int r = 0; r < rem; r++) {
        ulonglong2 kr = *reinterpret_cast<const ulonglong2*>(kp + r * 8 * HD);
        ulonglong2 vr = *reinterpret_cast<const ulonglong2*>(vp + r * 8 * HD);
        process(kr, vr);
    }
    if (last_warp) {   // key 2047 = new roped K/V from smem
        ulonglong2 kr = *reinterpret_cast<const ulonglong2*>(sk + 4 * lane);
        ulonglong2 vr = *reinterpret_cast<const ulonglong2*>(sv + 4 * lane);
        process(kr, vr);
    }

    // cross-warp reduce + normalize + direct write to g_attn
    __shared__ __align__(16) float sm_acc[8][G * HD];
    __shared__ float sm_s[8][G];
#pragma unroll
    for (int g = 0; g < G; g++) {
        float2 lo = unpack2(acc2[g][0]);
        float2 hi = unpack2(acc2[g][1]);
        float4 o;
        o.x = lo.x; o.y = lo.y; o.z = hi.x; o.w = hi.y;
        *reinterpret_cast<float4*>(&sm_acc[w][g * HD + lane * 4]) = o;
    }
    if ((lane & 7) == 0) sm_s[w][lane >> 3] = ssum;
    __syncthreads();

    // 512 output floats = 128 float4s: threads 0..127 only
    if (tid < 128) {
        const int t = tid;
        const int g = t >> 5;
        float s = 0.f;
#pragma unroll
        for (int ww = 0; ww < 8; ww++) s += sm_s[ww][g];
        float4 v = make_float4(0.f, 0.f, 0.f, 0.f);
#pragma unroll
        for (int ww = 0; ww < 8; ww++) {
            float4 a = *reinterpret_cast<const float4*>(&sm_acc[ww][t * 4]);
            v.x += a.x; v.y += a.y; v.z += a.z; v.w += a.w;
        }
        float inv = 1.f / s;
        v.x *= inv; v.y *= inv; v.z *= inv; v.w *= inv;
        *reinterpret_cast<float4*>(
            g_attn + (size_t)b * NQ + hkv * (G * HD) + t * 4) = v;
    }
}

__global__ void __launch_bounds__(256)
out_reduce_kernel(float* __restrict__ out)
{
    int idx = blockIdx.x * blockDim.x + threadIdx.x;
    float4 v = make_float4(0.f, 0.f, 0.f, 0.f);
#pragma unroll
    for (int s = 0; s < KSW; s++) {
        float4 a = *reinterpret_cast<const float4*>(
            g_out_part + (size_t)s * B * D + idx * 4);
        v.x += a.x; v.y += a.y; v.z += a.z; v.w += a.w;
    }
    *reinterpret_cast<float4*>(out + (size_t)idx * 4) = v;
}

// -------------------- launch (4 kernels; out_reduce at profiled idx 3) -------
extern "C" void kernel_launch(void* const* d_in, const int* in_sizes, int n_in,
                              void* d_out, int out_size)
{
    const float* x  = (const float*)d_in[0];
    const float* ck = (const float*)d_in[1];
    const float* cv = (const float*)d_in[2];
    const float* wq = (const float*)d_in[3];
    const float* wk = (const float*)d_in[4];
    const float* wv = (const float*)d_in[5];
    const float* wo = (const float*)d_in[6];
    const float* fc = (const float*)d_in[7];
    const float* fs = (const float*)d_in[8];
    float* out = (float*)d_out;

    dim3 gq(NTOT / 256, KSQ);
    gemm_qkv_kernel<<<gq, 128>>>(x, wq, wk, wv);                   // idx 0

    attn_kernel<<<B * HKV, 256>>>(ck, cv, fc, fs);                 // idx 1

    dim3 gw(D / 256, KSW);
    gemm_wo_kernel<<<gw, 128>>>(wo);                               // idx 2

    out_reduce_kernel<<<(B * D / 4) / 256, 256>>>(out);            // idx 3 (profiled)
}